// round 10
// baseline (speedup 1.0000x reference)
#include <cuda_runtime.h>
#include <cstdint>

#define NB 4
#define NN 2048
#define NC 768
#define NH 12
#define ND 64
#define WPAIR (NC * NC / 2)        // 294912 uint32 pairs per weight matrix
#define XPAIR (NB * NN * NC / 2)   // 3145728
#define QPAIR (NB * NH * NN * ND / 2)

// ---------------- scratch (device globals; no allocation allowed) ----------
__device__ uint32_t g_wh[4 * WPAIR], g_wl[4 * WPAIR];    // Wq,Wk,Wv,Wo bf16 hi/lo
__device__ uint32_t g_x1h[XPAIR], g_x1l[XPAIR];
__device__ uint32_t g_x2h[XPAIR], g_x2l[XPAIR];
__device__ uint32_t g_qh[QPAIR], g_ql[QPAIR];            // [B,H,N,D] (scaled by 0.125)
__device__ uint32_t g_kh[QPAIR], g_kl[QPAIR];
__device__ uint32_t g_vh[QPAIR], g_vl[QPAIR];
__device__ uint32_t g_aoh[XPAIR], g_aol[XPAIR];          // attention out [B*N, C]
__device__ float    g_t[NB * NN * NC];                   // oproj out (fp32 for LN)

// ======================= helpers (sm_80-level PTX only) =====================
static __device__ __forceinline__ uint32_t smem_u32(const void* p) {
    uint32_t a;
    asm("{ .reg .u64 t; cvta.to.shared.u64 t, %1; cvt.u32.u64 %0, t; }"
        : "=r"(a) : "l"(p));
    return a;
}
static __device__ __forceinline__ uint32_t pk(float lo, float hi) {
    uint32_t r;
    asm("cvt.rn.bf16x2.f32 %0, %1, %2;" : "=r"(r) : "f"(hi), "f"(lo));
    return r;
}
static __device__ __forceinline__ float lof(uint32_t u) { return __uint_as_float(u << 16); }
static __device__ __forceinline__ float hif(uint32_t u) { return __uint_as_float(u & 0xffff0000u); }

static __device__ __forceinline__ void ldsm4(uint32_t a, uint32_t* r) {
    asm volatile("ldmatrix.sync.aligned.m8n8.x4.shared.b16 {%0,%1,%2,%3}, [%4];"
                 : "=r"(r[0]), "=r"(r[1]), "=r"(r[2]), "=r"(r[3]) : "r"(a));
}
static __device__ __forceinline__ void ldsm4t(uint32_t a, uint32_t* r) {
    asm volatile("ldmatrix.sync.aligned.m8n8.x4.trans.shared.b16 {%0,%1,%2,%3}, [%4];"
                 : "=r"(r[0]), "=r"(r[1]), "=r"(r[2]), "=r"(r[3]) : "r"(a));
}
static __device__ __forceinline__ void mma_bf(float* c, const uint32_t* a, const uint32_t* b) {
    asm volatile("mma.sync.aligned.m16n8k16.row.col.f32.bf16.bf16.f32 "
                 "{%0,%1,%2,%3},{%4,%5,%6,%7},{%8,%9},{%0,%1,%2,%3};"
                 : "+f"(c[0]), "+f"(c[1]), "+f"(c[2]), "+f"(c[3])
                 : "r"(a[0]), "r"(a[1]), "r"(a[2]), "r"(a[3]),
                   "r"(b[0]), "r"(b[1]));
}
#define CPA(dst, src) \
    asm volatile("cp.async.cg.shared.global [%0], [%1], 16;" :: "r"(dst), "l"(src))
#define CPC() asm volatile("cp.async.commit_group;" ::: "memory")
#define CPW(n) asm volatile("cp.async.wait_group %0;" :: "n"(n) : "memory")

// swizzled smem byte offsets (16B granules, conflict-free ldmatrix)
#define GOFF(r, ch) ((((r) >> 1) * 128) + ((((((r) & 1) << 2) | (ch)) ^ (((r) >> 1) & 7)) * 16))
#define AOFF(r, ch) (((r) * 128) + ((((ch) ^ ((r) & 7))) * 16))

// ======================= prep: fused fp32 -> bf16 hi/lo split ===============
#define XN4 (NB * NN * NC / 4)
#define WN4 (NC * NC / 4)
#define TOT4 (2 * XN4 + 4 * WN4)

__global__ __launch_bounds__(256) void split_all(
    const float* __restrict__ x1, const float* __restrict__ x2,
    const float* __restrict__ Wq, const float* __restrict__ Wk,
    const float* __restrict__ Wv, const float* __restrict__ Wo)
{
    int i = blockIdx.x * blockDim.x + threadIdx.x;
    if (i >= TOT4) return;
    const float* src; uint32_t *dh, *dl; int li;
    if (i < XN4)          { src = x1; dh = g_x1h; dl = g_x1l; li = i; }
    else if (i < 2 * XN4) { src = x2; dh = g_x2h; dl = g_x2l; li = i - XN4; }
    else {
        int j = i - 2 * XN4;
        int w = j / WN4;
        li = j - w * WN4;
        src = (w == 0) ? Wq : (w == 1) ? Wk : (w == 2) ? Wv : Wo;
        dh = g_wh + (size_t)w * WPAIR;
        dl = g_wl + (size_t)w * WPAIR;
    }
    float4 f = ((const float4*)src)[li];
    uint32_t h0 = pk(f.x, f.y), h1 = pk(f.z, f.w);
    uint32_t l0 = pk(f.x - lof(h0), f.y - hif(h0));
    uint32_t l1 = pk(f.z - lof(h1), f.w - hif(h1));
    ((uint2*)dh)[li] = make_uint2(h0, h1);
    ((uint2*)dl)[li] = make_uint2(l0, l1);
}

// ======================= split-bf16 mma GEMM =================================
// C[M,768] = A @ W^T + bias. CTA 128x128, BK=32, 4 warps (2M x 2N), warp 64x64.
// 2-stage cp.async (64KB smem), dense per-warp MMA streams (192 MMA/chunk,
// 32 independent acc chains) for issue density. 2 CTA/SM.
#define GEMM_SMEM 65536

static __device__ __forceinline__ void gemm_issue(
    uint32_t sb, int buf, int c, const uint32_t* Ah, const uint32_t* Al,
    const uint32_t* Wh, const uint32_t* Wl, int m0, int n0, int tid)
{
#pragma unroll
    for (int p = 0; p < 4; p++) {
        int cid = tid + p * 128;
        int r = cid >> 2, ch = cid & 3;
        size_t sa = (size_t)(m0 + r) * 384 + c * 16 + ch * 4;
        size_t sw = (size_t)(n0 + r) * 384 + c * 16 + ch * 4;
        uint32_t d = sb + buf * 32768 + GOFF(r, ch);
        CPA(d,         Ah + sa);
        CPA(d + 8192,  Al + sa);
        CPA(d + 16384, Wh + sw);
        CPA(d + 24576, Wl + sw);
    }
}

__global__ __launch_bounds__(128) void mma_gemm3(
    const float* __restrict__ bq, const float* __restrict__ bk,
    const float* __restrict__ bv, const float* __restrict__ bo, int phase)
{
    extern __shared__ __align__(128) char gsm[];
    const uint32_t sb = smem_u32(gsm);
    const int mode = phase ? 3 : (int)blockIdx.z;
    const uint32_t* Ah = (mode == 0) ? g_x1h : (mode == 3) ? g_aoh : g_x2h;
    const uint32_t* Al = (mode == 0) ? g_x1l : (mode == 3) ? g_aol : g_x2l;
    const uint32_t* Wh = g_wh + (size_t)mode * WPAIR;
    const uint32_t* Wl = g_wl + (size_t)mode * WPAIR;
    const float* bias = (mode == 0) ? bq : (mode == 1) ? bk : (mode == 2) ? bv : bo;

    const int n0 = blockIdx.x * 128;
    const int m0 = blockIdx.y * 128;
    const int tid  = threadIdx.x;
    const int lane = tid & 31;
    const int wid  = tid >> 5;       // 0..3
    const int wm = wid & 1;          // 2 warps over M (64 rows each)
    const int wn = wid >> 1;         // 2 warps over N (64 cols each)
    const int g  = lane >> 2;
    const int t  = lane & 3;
    const int lr = lane & 15;
    const int lc = lane >> 4;

    float acc[4][8][4];
#pragma unroll
    for (int i = 0; i < 4; i++)
#pragma unroll
        for (int j = 0; j < 8; j++)
#pragma unroll
            for (int c = 0; c < 4; c++) acc[i][j][c] = 0.f;

    gemm_issue(sb, 0, 0, Ah, Al, Wh, Wl, m0, n0, tid); CPC();
    gemm_issue(sb, 1, 1, Ah, Al, Wh, Wl, m0, n0, tid); CPC();

    for (int c = 0; c < NC / 32; c++) {
        if (c + 1 < NC / 32) { CPW(1); } else { CPW(0); }
        __syncthreads();
        const uint32_t s2 = sb + (c & 1) * 32768;

#pragma unroll
        for (int ks = 0; ks < 2; ks++) {
            const int chk = ks * 2 + lc;
#pragma unroll
            for (int nh = 0; nh < 2; nh++) {
                // B frags for this 32-col half: 4 n-frags hi + lo
                uint32_t bh[4][2], bl[4][2];
#pragma unroll
                for (int jj = 0; jj < 2; jj++) {
                    uint32_t q[4];
                    ldsm4(s2 + 16384 + GOFF(wn * 64 + nh * 32 + jj * 16 + lr, chk), q);
                    bh[jj * 2][0] = q[0]; bh[jj * 2][1] = q[2];
                    bh[jj * 2 + 1][0] = q[1]; bh[jj * 2 + 1][1] = q[3];
                    ldsm4(s2 + 24576 + GOFF(wn * 64 + nh * 32 + jj * 16 + lr, chk), q);
                    bl[jj * 2][0] = q[0]; bl[jj * 2][1] = q[2];
                    bl[jj * 2 + 1][0] = q[1]; bl[jj * 2 + 1][1] = q[3];
                }
#pragma unroll
                for (int mf = 0; mf < 4; mf++) {
                    uint32_t ah[4], al[4];
                    ldsm4(s2 + GOFF(wm * 64 + mf * 16 + lr, chk), ah);
                    ldsm4(s2 + 8192 + GOFF(wm * 64 + mf * 16 + lr, chk), al);
#pragma unroll
                    for (int jn = 0; jn < 4; jn++) {
                        float* a2 = acc[mf][nh * 4 + jn];
                        mma_bf(a2, ah, bh[jn]);
                        mma_bf(a2, ah, bl[jn]);
                        mma_bf(a2, al, bh[jn]);
                    }
                }
            }
        }
        __syncthreads();
        if (c + 2 < NC / 32) {
            gemm_issue(sb, c & 1, c + 2, Ah, Al, Wh, Wl, m0, n0, tid); CPC();
        }
    }

    const float sc = (mode == 0) ? 0.125f : 1.0f;
    uint32_t* dqh = (mode == 0) ? g_qh : (mode == 1) ? g_kh : g_vh;
    uint32_t* dql = (mode == 0) ? g_ql : (mode == 1) ? g_kl : g_vl;
#pragma unroll
    for (int mf = 0; mf < 4; mf++) {
        int r = m0 + wm * 64 + mf * 16 + g;
#pragma unroll
        for (int j = 0; j < 8; j++) {
            int cg = n0 + wn * 64 + j * 8 + t * 2;
            float bx = bias[cg], by = bias[cg + 1];
            float2 v0 = { (acc[mf][j][0] + bx) * sc, (acc[mf][j][1] + by) * sc };
            float2 v1 = { (acc[mf][j][2] + bx) * sc, (acc[mf][j][3] + by) * sc };
            if (mode == 3) {
                *(float2*)(g_t + (size_t)r * NC + cg) = v0;
                *(float2*)(g_t + (size_t)(r + 8) * NC + cg) = v1;
            } else {
                int b = r >> 11, h = cg >> 6, dp = (cg & 63) >> 1;
                size_t base = ((size_t)(b * NH + h)) * NN;
                size_t i0 = (base + (r & (NN - 1))) * 32 + dp;
                size_t i1 = (base + ((r + 8) & (NN - 1))) * 32 + dp;
                uint32_t h0 = pk(v0.x, v0.y);
                uint32_t l0 = pk(v0.x - lof(h0), v0.y - hif(h0));
                uint32_t h1 = pk(v1.x, v1.y);
                uint32_t l1 = pk(v1.x - lof(h1), v1.y - hif(h1));
                dqh[i0] = h0; dql[i0] = l0;
                dqh[i1] = h1; dql[i1] = l1;
            }
        }
    }
}

// ======================= split-bf16 mma flash attention (R8, unchanged) =====
#define F_M2  0
#define F_RED 8192
#define F_QH  8704
#define F_QL  16896
#define F_KV  25088
#define F_OB  25088
#define ATT_SMEM (F_KV + 2 * 32768)       // 90624

static __device__ __forceinline__ void kv_issue(
    uint32_t sb, int buf, int it, const uint32_t* kh, const uint32_t* kl,
    const uint32_t* vh, const uint32_t* vl, int tid)
{
#pragma unroll
    for (int p = 0; p < 2; p++) {
        int cid = tid + p * 256;
        int r = cid >> 3, ch = cid & 7;
        size_t src = (size_t)(it * 64 + r) * 32 + ch * 4;
        uint32_t d = sb + F_KV + buf * 32768 + AOFF(r, ch);
        CPA(d,         kh + src);
        CPA(d + 8192,  kl + src);
        CPA(d + 16384, vh + src);
        CPA(d + 24576, vl + src);
    }
}

__global__ __launch_bounds__(256) void mma_flash2(
    const float* __restrict__ mask1, const float* __restrict__ mask2,
    const float* __restrict__ temp_p)
{
    extern __shared__ __align__(128) char sm[];
    const uint32_t sb = smem_u32(sm);
    const int mt = blockIdx.x;
    const int bh = blockIdx.y;
    const int b  = bh / NH;
    const int h  = bh % NH;
    const int tid  = threadIdx.x;
    const int lane = tid & 31;
    const int wid  = tid >> 5;
    const int wm = wid & 3;
    const int wn = wid >> 2;
    const int g  = lane >> 2;
    const int t  = lane & 3;
    const int lr = lane & 15;
    const int lc = lane >> 4;

    const float itemp = 1.0f / temp_p[0];

    const uint32_t* qhp = g_qh + ((size_t)bh * NN + mt * 64) * 32;
    const uint32_t* qlp = g_ql + ((size_t)bh * NN + mt * 64) * 32;
    const uint32_t* khp = g_kh + (size_t)bh * NN * 32;
    const uint32_t* klp = g_kl + (size_t)bh * NN * 32;
    const uint32_t* vhp = g_vh + (size_t)bh * NN * 32;
    const uint32_t* vlp = g_vl + (size_t)bh * NN * 32;

#pragma unroll
    for (int p = 0; p < 2; p++) {
        int cid = tid + p * 256;
        int r = cid >> 3, ch = cid & 7;
        size_t src = (size_t)r * 32 + ch * 4;
        CPA(sb + F_QH + AOFF(r, ch), qhp + src);
        CPA(sb + F_QL + AOFF(r, ch), qlp + src);
    }
    CPC();
    kv_issue(sb, 0, 0, khp, klp, vhp, vlp, tid); CPC();
    kv_issue(sb, 1, 1, khp, klp, vhp, vlp, tid); CPC();

    float* m2s = (float*)(sm + F_M2);
    for (int i = tid; i < NN / 4; i += 256) {
        float4 f = *(const float4*)(mask2 + b * NN + i * 4);
        float4 gg = { f.x * itemp, f.y * itemp, f.z * itemp, f.w * itemp };
        *(float4*)(m2s + i * 4) = gg;
    }

    CPW(2);
    __syncthreads();

    uint32_t qh[4][4], ql[4][4];
#pragma unroll
    for (int ks = 0; ks < 4; ks++) {
        ldsm4(sb + F_QH + AOFF(wm * 16 + lr, ks * 2 + lc), qh[ks]);
        ldsm4(sb + F_QL + AOFF(wm * 16 + lr, ks * 2 + lc), ql[ks]);
    }

    const float m1r0 = mask1[b * NN + mt * 64 + wm * 16 + g] * itemp;
    const float m1r1 = mask1[b * NN + mt * 64 + wm * 16 + 8 + g] * itemp;

    float o[8][4];
#pragma unroll
    for (int j = 0; j < 8; j++)
#pragma unroll
        for (int c = 0; c < 4; c++) o[j][c] = 0.f;
    float mst0 = -1e30f, mst1 = -1e30f, l0 = 0.f, l1 = 0.f;

    float* red = (float*)(sm + F_RED);
    const int r0 = wm * 16 + g;

    for (int it = 0; it < NN / 64; it++) {
        if (it + 1 < NN / 64) { CPW(1); } else { CPW(0); }
        __syncthreads();
        const uint32_t skv = sb + F_KV + (it & 1) * 32768;

        float s[4][4];
#pragma unroll
        for (int j = 0; j < 4; j++)
#pragma unroll
            for (int c = 0; c < 4; c++) s[j][c] = 0.f;
#pragma unroll
        for (int ks = 0; ks < 4; ks++) {
            const int chk = ks * 2 + lc;
            uint32_t bhf[4][2], blf[4][2];
#pragma unroll
            for (int jj = 0; jj < 2; jj++) {
                uint32_t q[4];
                ldsm4(skv + AOFF(wn * 32 + jj * 16 + lr, chk), q);
                bhf[jj * 2][0] = q[0]; bhf[jj * 2][1] = q[2];
                bhf[jj * 2 + 1][0] = q[1]; bhf[jj * 2 + 1][1] = q[3];
                ldsm4(skv + 8192 + AOFF(wn * 32 + jj * 16 + lr, chk), q);
                blf[jj * 2][0] = q[0]; blf[jj * 2][1] = q[2];
                blf[jj * 2 + 1][0] = q[1]; blf[jj * 2 + 1][1] = q[3];
            }
#pragma unroll
            for (int j = 0; j < 4; j++) {
                mma_bf(s[j], qh[ks], bhf[j]);
                mma_bf(s[j], qh[ks], blf[j]);
                mma_bf(s[j], ql[ks], bhf[j]);
            }
        }

        float mx0 = -1e30f, mx1 = -1e30f;
#pragma unroll
        for (int j = 0; j < 4; j++) {
            float2 mm = *(float2*)(m2s + it * 64 + wn * 32 + j * 8 + t * 2);
            s[j][0] = s[j][0] + m1r0 - mm.x;
            s[j][1] = s[j][1] + m1r0 - mm.y;
            s[j][2] = s[j][2] + m1r1 - mm.x;
            s[j][3] = s[j][3] + m1r1 - mm.y;
            mx0 = fmaxf(mx0, fmaxf(s[j][0], s[j][1]));
            mx1 = fmaxf(mx1, fmaxf(s[j][2], s[j][3]));
        }
        mx0 = fmaxf(mx0, __shfl_xor_sync(0xffffffffu, mx0, 1));
        mx0 = fmaxf(mx0, __shfl_xor_sync(0xffffffffu, mx0, 2));
        mx1 = fmaxf(mx1, __shfl_xor_sync(0xffffffffu, mx1, 1));
        mx1 = fmaxf(mx1, __shfl_xor_sync(0xffffffffu, mx1, 2));

        float mn0 = fmaxf(mst0, mx0), mn1 = fmaxf(mst1, mx1);
        float c0 = __expf(mst0 - mn0), c1 = __expf(mst1 - mn1);
        mst0 = mn0; mst1 = mn1;

        float rs0 = 0.f, rs1 = 0.f;
#pragma unroll
        for (int j = 0; j < 4; j++) {
            s[j][0] = __expf(s[j][0] - mn0);
            s[j][1] = __expf(s[j][1] - mn0);
            s[j][2] = __expf(s[j][2] - mn1);
            s[j][3] = __expf(s[j][3] - mn1);
            rs0 += s[j][0] + s[j][1];
            rs1 += s[j][2] + s[j][3];
        }
        rs0 += __shfl_xor_sync(0xffffffffu, rs0, 1);
        rs0 += __shfl_xor_sync(0xffffffffu, rs0, 2);
        rs1 += __shfl_xor_sync(0xffffffffu, rs1, 1);
        rs1 += __shfl_xor_sync(0xffffffffu, rs1, 2);
        l0 = l0 * c0 + rs0;
        l1 = l1 * c1 + rs1;
#pragma unroll
        for (int j = 0; j < 8; j++) {
            o[j][0] *= c0; o[j][1] *= c0;
            o[j][2] *= c1; o[j][3] *= c1;
        }

#pragma unroll
        for (int kks = 0; kks < 2; kks++) {
            const int j0 = 2 * kks, j1 = j0 + 1;
            uint32_t pah[4], pal[4];
            pah[0] = pk(s[j0][0], s[j0][1]);
            pah[1] = pk(s[j0][2], s[j0][3]);
            pah[2] = pk(s[j1][0], s[j1][1]);
            pah[3] = pk(s[j1][2], s[j1][3]);
            pal[0] = pk(s[j0][0] - lof(pah[0]), s[j0][1] - hif(pah[0]));
            pal[1] = pk(s[j0][2] - lof(pah[1]), s[j0][3] - hif(pah[1]));
            pal[2] = pk(s[j1][0] - lof(pah[2]), s[j1][1] - hif(pah[2]));
            pal[3] = pk(s[j1][2] - lof(pah[3]), s[j1][3] - hif(pah[3]));

            uint32_t vhf[8][2], vlf[8][2];
#pragma unroll
            for (int jj = 0; jj < 4; jj++) {
                uint32_t q[4];
                ldsm4t(skv + 16384 + AOFF(wn * 32 + kks * 16 + lr, jj * 2 + lc), q);
                vhf[jj * 2][0] = q[0]; vhf[jj * 2][1] = q[1];
                vhf[jj * 2 + 1][0] = q[2]; vhf[jj * 2 + 1][1] = q[3];
                ldsm4t(skv + 24576 + AOFF(wn * 32 + kks * 16 + lr, jj * 2 + lc), q);
                vlf[jj * 2][0] = q[0]; vlf[jj * 2][1] = q[1];
                vlf[jj * 2 + 1][0] = q[2]; vlf[jj * 2 + 1][1] = q[3];
            }
#pragma unroll
            for (int j = 0; j < 8; j++) {
                mma_bf(o[j], pah, vhf[j]);
                mma_bf(o[j], pah, vlf[j]);
                mma_bf(o[j], pal, vhf[j]);
            }
        }

        __syncthreads();
        if (it + 2 < NN / 64) {
            kv_issue(sb, it & 1, it + 2, khp, klp, vhp, vlp, tid); CPC();
        }
    }

    __syncthreads();
    float* ob = (float*)(sm + F_OB);
    if (wn == 1) {
#pragma unroll
        for (int j = 0; j < 8; j++) {
            *(float2*)(ob + r0 * 68 + j * 8 + t * 2) = make_float2(o[j][0], o[j][1]);
            *(float2*)(ob + (r0 + 8) * 68 + j * 8 + t * 2) = make_float2(o[j][2], o[j][3]);
        }
        if (t == 0) {
            red[r0]      = l0;   red[r0 + 8]      = l1;
            red[64 + r0] = mst0; red[64 + r0 + 8] = mst1;
        }
    }
    __syncthreads();
    if (wn == 0) {
        float mB0 = red[64 + r0], mB1 = red[64 + r0 + 8];
        float lB0 = red[r0],      lB1 = red[r0 + 8];
        float m0f = fmaxf(mst0, mB0), m1f = fmaxf(mst1, mB1);
        float cA0 = __expf(mst0 - m0f), cB0 = __expf(mB0 - m0f);
        float cA1 = __expf(mst1 - m1f), cB1 = __expf(mB1 - m1f);
        float inv0 = 1.0f / (l0 * cA0 + lB0 * cB0);
        float inv1 = 1.0f / (l1 * cA1 + lB1 * cB1);
#pragma unroll
        for (int j = 0; j < 8; j++) {
            float2 u0 = *(float2*)(ob + r0 * 68 + j * 8 + t * 2);
            float2 u1 = *(float2*)(ob + (r0 + 8) * 68 + j * 8 + t * 2);
            float2 w0 = make_float2((o[j][0] * cA0 + u0.x * cB0) * inv0,
                                    (o[j][1] * cA0 + u0.y * cB0) * inv0);
            float2 w1 = make_float2((o[j][2] * cA1 + u1.x * cB1) * inv1,
                                    (o[j][3] * cA1 + u1.y * cB1) * inv1);
            size_t i0 = (size_t)(b * NN + mt * 64 + r0) * 384 + h * 32 + j * 4 + t;
            size_t i1 = (size_t)(b * NN + mt * 64 + r0 + 8) * 384 + h * 32 + j * 4 + t;
            uint32_t h0 = pk(w0.x, w0.y);
            uint32_t l0u = pk(w0.x - lof(h0), w0.y - hif(h0));
            uint32_t h1 = pk(w1.x, w1.y);
            uint32_t l1u = pk(w1.x - lof(h1), w1.y - hif(h1));
            g_aoh[i0] = h0; g_aol[i0] = l0u;
            g_aoh[i1] = h1; g_aol[i1] = l1u;
        }
    }
}

// ---------------------------------------------------------------------------
// LayerNorm(0.5*x1 + g_t)
// ---------------------------------------------------------------------------
__global__ __launch_bounds__(256) void ln_kernel(
    const float* __restrict__ x1, const float* __restrict__ gamma,
    const float* __restrict__ beta, float* __restrict__ out)
{
    const int row = blockIdx.x;
    const int tid = threadIdx.x;
    const float* tr = g_t + (size_t)row * NC;
    const float* xr = x1 + (size_t)row * NC;

    float z[3];
    float s = 0.f;
#pragma unroll
    for (int u = 0; u < 3; u++) {
        int idx = tid + u * 256;
        z[u] = 0.5f * xr[idx] + tr[idx];
        s += z[u];
    }

    __shared__ float red[8];
#pragma unroll
    for (int off = 16; off >= 1; off >>= 1) s += __shfl_xor_sync(0xffffffffu, s, off);
    if ((tid & 31) == 0) red[tid >> 5] = s;
    __syncthreads();
    float tot = 0.f;
#pragma unroll
    for (int w = 0; w < 8; w++) tot += red[w];
    const float mu = tot * (1.0f / NC);

    float s2 = 0.f;
#pragma unroll
    for (int u = 0; u < 3; u++) {
        float d = z[u] - mu;
        s2 += d * d;
    }
    __syncthreads();
#pragma unroll
    for (int off = 16; off >= 1; off >>= 1) s2 += __shfl_xor_sync(0xffffffffu, s2, off);
    if ((tid & 31) == 0) red[tid >> 5] = s2;
    __syncthreads();
    float tot2 = 0.f;
#pragma unroll
    for (int w = 0; w < 8; w++) tot2 += red[w];
    const float rstd = rsqrtf(tot2 * (1.0f / NC) + 1e-5f);

    float* orow = out + (size_t)row * NC;
#pragma unroll
    for (int u = 0; u < 3; u++) {
        int idx = tid + u * 256;
        orow[idx] = (z[u] - mu) * rstd * gamma[idx] + beta[idx];
    }
}

// ---------------------------------------------------------------------------
extern "C" void kernel_launch(void* const* d_in, const int* in_sizes, int n_in,
                              void* d_out, int out_size)
{
    (void)in_sizes; (void)n_in; (void)out_size;
    const float* x1    = (const float*)d_in[0];
    const float* x2    = (const float*)d_in[1];
    const float* mask1 = (const float*)d_in[2];
    const float* mask2 = (const float*)d_in[3];
    const float* Wq    = (const float*)d_in[4];
    const float* bq    = (const float*)d_in[5];
    const float* Wk    = (const float*)d_in[6];
    const float* bk    = (const float*)d_in[7];
    const float* Wv    = (const float*)d_in[8];
    const float* bv    = (const float*)d_in[9];
    const float* Wo    = (const float*)d_in[10];
    const float* bo    = (const float*)d_in[11];
    const float* temp  = (const float*)d_in[12];
    const float* gamma = (const float*)d_in[13];
    const float* beta  = (const float*)d_in[14];
    float* out = (float*)d_out;

    cudaFuncSetAttribute(mma_flash2,
                         cudaFuncAttributeMaxDynamicSharedMemorySize, ATT_SMEM);
    cudaFuncSetAttribute(mma_gemm3,
                         cudaFuncAttributeMaxDynamicSharedMemorySize, GEMM_SMEM);

    // prep: fused fp32 -> bf16 hi/lo split (single launch)
    split_all<<<(TOT4 + 255) / 256, 256>>>(x1, x2, Wq, Wk, Wv, Wo);

    // QKV projections
    mma_gemm3<<<dim3(NC / 128, (NB * NN) / 128, 3), 128, GEMM_SMEM>>>(bq, bk, bv, bo, 0);
    // attention
    mma_flash2<<<dim3(NN / 64, NB * NH), 256, ATT_SMEM>>>(mask1, mask2, temp);
    // output projection
    mma_gemm3<<<dim3(NC / 128, (NB * NN) / 128, 1), 128, GEMM_SMEM>>>(bq, bk, bv, bo, 1);
    ln_kernel<<<NB * NN, 256>>>(x1, gamma, beta, out);
}

// round 11
// speedup vs baseline: 1.4274x; 1.4274x over previous
#include <cuda_runtime.h>
#include <cstdint>

#define NB 4
#define NN 2048
#define NC 768
#define NH 12
#define ND 64
#define WPAIR (NC * NC / 2)        // 294912 uint32 pairs per weight matrix
#define XPAIR (NB * NN * NC / 2)   // 3145728
#define QPAIR (NB * NH * NN * ND / 2)

// ---------------- scratch (device globals; no allocation allowed) ----------
__device__ uint32_t g_wh[4 * WPAIR];                     // weights: fp16 hi only (B side)
__device__ uint32_t g_x1h[XPAIR], g_x1l[XPAIR];          // activations: fp16 hi+lo (A side)
__device__ uint32_t g_x2h[XPAIR], g_x2l[XPAIR];
__device__ uint32_t g_qh[QPAIR], g_ql[QPAIR];            // Q: hi+lo (A side, x0.125)
__device__ uint32_t g_kh[QPAIR];                         // K: hi only (B side)
__device__ uint32_t g_vh[QPAIR];                         // V: hi only (B side)
__device__ uint32_t g_aoh[XPAIR], g_aol[XPAIR];          // attention out: hi+lo (A side)
__device__ float    g_t[NB * NN * NC];                   // oproj out (fp32 for LN)

// ======================= helpers (sm_80-level PTX only) =====================
static __device__ __forceinline__ uint32_t smem_u32(const void* p) {
    uint32_t a;
    asm("{ .reg .u64 t; cvta.to.shared.u64 t, %1; cvt.u32.u64 %0, t; }"
        : "=r"(a) : "l"(p));
    return a;
}
// pack two fp32 -> fp16x2 (lo in low half)
static __device__ __forceinline__ uint32_t pkh(float lo, float hi) {
    uint32_t r;
    asm("cvt.rn.f16x2.f32 %0, %1, %2;" : "=r"(r) : "f"(hi), "f"(lo));
    return r;
}
static __device__ __forceinline__ float lofH(uint32_t u) {
    float f;
    asm("{ .reg .b16 l, h; mov.b32 {l, h}, %1; cvt.f32.f16 %0, l; }"
        : "=f"(f) : "r"(u));
    return f;
}
static __device__ __forceinline__ float hifH(uint32_t u) {
    float f;
    asm("{ .reg .b16 l, h; mov.b32 {l, h}, %1; cvt.f32.f16 %0, h; }"
        : "=f"(f) : "r"(u));
    return f;
}
static __device__ __forceinline__ void ldsm4(uint32_t a, uint32_t* r) {
    asm volatile("ldmatrix.sync.aligned.m8n8.x4.shared.b16 {%0,%1,%2,%3}, [%4];"
                 : "=r"(r[0]), "=r"(r[1]), "=r"(r[2]), "=r"(r[3]) : "r"(a));
}
static __device__ __forceinline__ void ldsm4t(uint32_t a, uint32_t* r) {
    asm volatile("ldmatrix.sync.aligned.m8n8.x4.trans.shared.b16 {%0,%1,%2,%3}, [%4];"
                 : "=r"(r[0]), "=r"(r[1]), "=r"(r[2]), "=r"(r[3]) : "r"(a));
}
static __device__ __forceinline__ void mma_hf(float* c, const uint32_t* a, const uint32_t* b) {
    asm volatile("mma.sync.aligned.m16n8k16.row.col.f32.f16.f16.f32 "
                 "{%0,%1,%2,%3},{%4,%5,%6,%7},{%8,%9},{%0,%1,%2,%3};"
                 : "+f"(c[0]), "+f"(c[1]), "+f"(c[2]), "+f"(c[3])
                 : "r"(a[0]), "r"(a[1]), "r"(a[2]), "r"(a[3]),
                   "r"(b[0]), "r"(b[1]));
}
#define CPA(dst, src) \
    asm volatile("cp.async.cg.shared.global [%0], [%1], 16;" :: "r"(dst), "l"(src))
#define CPC() asm volatile("cp.async.commit_group;" ::: "memory")
#define CPW(n) asm volatile("cp.async.wait_group %0;" :: "n"(n) : "memory")

// swizzled smem byte offsets (16B granules, conflict-free ldmatrix)
#define GOFF(r, ch) ((((r) >> 1) * 128) + ((((((r) & 1) << 2) | (ch)) ^ (((r) >> 1) & 7)) * 16))
#define AOFF(r, ch) (((r) * 128) + ((((ch) ^ ((r) & 7))) * 16))

// ======================= prep: fused fp32 -> fp16 split =====================
#define XN4 (NB * NN * NC / 4)
#define WN4 (NC * NC / 4)
#define TOT4 (2 * XN4 + 4 * WN4)

__global__ __launch_bounds__(256) void split_all(
    const float* __restrict__ x1, const float* __restrict__ x2,
    const float* __restrict__ Wq, const float* __restrict__ Wk,
    const float* __restrict__ Wv, const float* __restrict__ Wo)
{
    int i = blockIdx.x * blockDim.x + threadIdx.x;
    if (i >= TOT4) return;
    if (i < 2 * XN4) {
        const float* src = (i < XN4) ? x1 : x2;
        uint32_t* dh = (i < XN4) ? g_x1h : g_x2h;
        uint32_t* dl = (i < XN4) ? g_x1l : g_x2l;
        int li = (i < XN4) ? i : i - XN4;
        float4 f = ((const float4*)src)[li];
        uint32_t h0 = pkh(f.x, f.y), h1 = pkh(f.z, f.w);
        uint32_t l0 = pkh(f.x - lofH(h0), f.y - hifH(h0));
        uint32_t l1 = pkh(f.z - lofH(h1), f.w - hifH(h1));
        ((uint2*)dh)[li] = make_uint2(h0, h1);
        ((uint2*)dl)[li] = make_uint2(l0, l1);
    } else {
        int j = i - 2 * XN4;
        int w = j / WN4;
        int li = j - w * WN4;
        const float* src = (w == 0) ? Wq : (w == 1) ? Wk : (w == 2) ? Wv : Wo;
        uint32_t* dh = g_wh + (size_t)w * WPAIR;
        float4 f = ((const float4*)src)[li];
        ((uint2*)dh)[li] = make_uint2(pkh(f.x, f.y), pkh(f.z, f.w));
    }
}

// ======================= fp16 2-term mma GEMM ================================
// C[M,768] = A @ W^T + bias; D = Ah*Wh + Al*Wh (W hi only).
// CTA 128x128, BK=32, 8 warps (4M x 2N). 2-stage cp.async.
// stage: Ahi 8K | Alo 8K | Bhi 8K = 24KB; 2 stages = 48KB.
#define GSTG 24576
#define GEMM_SMEM (2 * GSTG)      // 49152

static __device__ __forceinline__ void gemm_issue(
    uint32_t sb, int buf, int c, const uint32_t* Ah, const uint32_t* Al,
    const uint32_t* Wh, int m0, int n0, int tid)
{
#pragma unroll
    for (int p = 0; p < 2; p++) {
        int cid = tid + p * 256;
        int r = cid >> 2, ch = cid & 3;
        size_t sa = (size_t)(m0 + r) * 384 + c * 16 + ch * 4;
        size_t sw = (size_t)(n0 + r) * 384 + c * 16 + ch * 4;
        uint32_t d = sb + buf * GSTG + GOFF(r, ch);
        CPA(d,         Ah + sa);
        CPA(d + 8192,  Al + sa);
        CPA(d + 16384, Wh + sw);
    }
}

__global__ __launch_bounds__(256) void mma_gemm2(
    const float* __restrict__ bq, const float* __restrict__ bk,
    const float* __restrict__ bv, const float* __restrict__ bo, int phase)
{
    extern __shared__ __align__(128) char gsm[];
    const uint32_t sb = smem_u32(gsm);
    const int mode = phase ? 3 : (int)blockIdx.z;
    const uint32_t* Ah = (mode == 0) ? g_x1h : (mode == 3) ? g_aoh : g_x2h;
    const uint32_t* Al = (mode == 0) ? g_x1l : (mode == 3) ? g_aol : g_x2l;
    const uint32_t* Wh = g_wh + (size_t)mode * WPAIR;
    const float* bias = (mode == 0) ? bq : (mode == 1) ? bk : (mode == 2) ? bv : bo;

    const int n0 = blockIdx.x * 128;
    const int m0 = blockIdx.y * 128;
    const int tid  = threadIdx.x;
    const int lane = tid & 31;
    const int wid  = tid >> 5;
    const int wm = wid & 3;
    const int wn = wid >> 2;
    const int g  = lane >> 2;
    const int t  = lane & 3;
    const int lr = lane & 15;
    const int lc = lane >> 4;

    float acc[2][8][4];
#pragma unroll
    for (int i = 0; i < 2; i++)
#pragma unroll
        for (int j = 0; j < 8; j++)
#pragma unroll
            for (int c = 0; c < 4; c++) acc[i][j][c] = 0.f;

    gemm_issue(sb, 0, 0, Ah, Al, Wh, m0, n0, tid); CPC();
    gemm_issue(sb, 1, 1, Ah, Al, Wh, m0, n0, tid); CPC();

    for (int c = 0; c < NC / 32; c++) {
        if (c + 1 < NC / 32) { CPW(1); } else { CPW(0); }
        __syncthreads();
        const uint32_t s2 = sb + (c & 1) * GSTG;

#pragma unroll
        for (int ks = 0; ks < 2; ks++) {
            const int chk = ks * 2 + lc;
            uint32_t ah[2][4], al[2][4], bh[8][2];
#pragma unroll
            for (int mf = 0; mf < 2; mf++) {
                ldsm4(s2 + GOFF(wm * 32 + mf * 16 + lr, chk), ah[mf]);
                ldsm4(s2 + 8192 + GOFF(wm * 32 + mf * 16 + lr, chk), al[mf]);
            }
#pragma unroll
            for (int jj = 0; jj < 4; jj++) {
                uint32_t q[4];
                ldsm4(s2 + 16384 + GOFF(wn * 64 + jj * 16 + lr, chk), q);
                bh[jj * 2][0] = q[0]; bh[jj * 2][1] = q[2];
                bh[jj * 2 + 1][0] = q[1]; bh[jj * 2 + 1][1] = q[3];
            }
#pragma unroll
            for (int mf = 0; mf < 2; mf++)
#pragma unroll
                for (int j = 0; j < 8; j++) {
                    mma_hf(acc[mf][j], ah[mf], bh[j]);
                    mma_hf(acc[mf][j], al[mf], bh[j]);
                }
        }
        __syncthreads();
        if (c + 2 < NC / 32) {
            gemm_issue(sb, c & 1, c + 2, Ah, Al, Wh, m0, n0, tid); CPC();
        }
    }

#pragma unroll
    for (int mf = 0; mf < 2; mf++) {
        int r = m0 + wm * 32 + mf * 16 + g;
#pragma unroll
        for (int j = 0; j < 8; j++) {
            int cg = n0 + wn * 64 + j * 8 + t * 2;
            float bx = bias[cg], by = bias[cg + 1];
            float2 v0 = { acc[mf][j][0] + bx, acc[mf][j][1] + by };
            float2 v1 = { acc[mf][j][2] + bx, acc[mf][j][3] + by };
            if (mode == 3) {
                *(float2*)(g_t + (size_t)r * NC + cg) = v0;
                *(float2*)(g_t + (size_t)(r + 8) * NC + cg) = v1;
            } else {
                int b = r >> 11, h = cg >> 6, dp = (cg & 63) >> 1;
                size_t base = ((size_t)(b * NH + h)) * NN;
                size_t i0 = (base + (r & (NN - 1))) * 32 + dp;
                size_t i1 = (base + ((r + 8) & (NN - 1))) * 32 + dp;
                if (mode == 0) {
                    v0.x *= 0.125f; v0.y *= 0.125f;
                    v1.x *= 0.125f; v1.y *= 0.125f;
                    uint32_t h0 = pkh(v0.x, v0.y);
                    uint32_t l0 = pkh(v0.x - lofH(h0), v0.y - hifH(h0));
                    uint32_t h1 = pkh(v1.x, v1.y);
                    uint32_t l1 = pkh(v1.x - lofH(h1), v1.y - hifH(h1));
                    g_qh[i0] = h0; g_ql[i0] = l0;
                    g_qh[i1] = h1; g_ql[i1] = l1;
                } else {
                    uint32_t* dst = (mode == 1) ? g_kh : g_vh;
                    dst[i0] = pkh(v0.x, v0.y);
                    dst[i1] = pkh(v1.x, v1.y);
                }
            }
        }
    }
}

// ======================= fp16 2-term mma flash attention =====================
// CTA 64 Q-rows; 8 warps 4(M)x2(N). Independent per-half online softmax,
// merged once in the epilogue. S = Qh*Kh + Ql*Kh; O += Ph*Vh + Pl*Vh.
// smem: m2 8K | red 512 | Qhi 8K | Qlo 8K | KV stages 2x16K (Kh|Vh)
#define F_M2  0
#define F_RED 8192
#define F_QH  8704
#define F_QL  16896
#define F_KV  25088
#define F_OB  25088                       // aliases KV (used only after loop)
#define FSTG  16384
#define ATT_SMEM (F_KV + 2 * FSTG)        // 57856

static __device__ __forceinline__ void kv_issue(
    uint32_t sb, int buf, int it, const uint32_t* kh, const uint32_t* vh, int tid)
{
#pragma unroll
    for (int p = 0; p < 2; p++) {
        int cid = tid + p * 256;
        int r = cid >> 3, ch = cid & 7;
        size_t src = (size_t)(it * 64 + r) * 32 + ch * 4;
        uint32_t d = sb + F_KV + buf * FSTG + AOFF(r, ch);
        CPA(d,         kh + src);
        CPA(d + 8192,  vh + src);
    }
}

__global__ __launch_bounds__(256) void mma_flash2(
    const float* __restrict__ mask1, const float* __restrict__ mask2,
    const float* __restrict__ temp_p)
{
    extern __shared__ __align__(128) char sm[];
    const uint32_t sb = smem_u32(sm);
    const int mt = blockIdx.x;
    const int bh = blockIdx.y;
    const int b  = bh / NH;
    const int h  = bh % NH;
    const int tid  = threadIdx.x;
    const int lane = tid & 31;
    const int wid  = tid >> 5;
    const int wm = wid & 3;
    const int wn = wid >> 2;
    const int g  = lane >> 2;
    const int t  = lane & 3;
    const int lr = lane & 15;
    const int lc = lane >> 4;

    const float itemp = 1.0f / temp_p[0];

    const uint32_t* qhp = g_qh + ((size_t)bh * NN + mt * 64) * 32;
    const uint32_t* qlp = g_ql + ((size_t)bh * NN + mt * 64) * 32;
    const uint32_t* khp = g_kh + (size_t)bh * NN * 32;
    const uint32_t* vhp = g_vh + (size_t)bh * NN * 32;

    // Q tiles (group 0)
#pragma unroll
    for (int p = 0; p < 2; p++) {
        int cid = tid + p * 256;
        int r = cid >> 3, ch = cid & 7;
        size_t src = (size_t)r * 32 + ch * 4;
        CPA(sb + F_QH + AOFF(r, ch), qhp + src);
        CPA(sb + F_QL + AOFF(r, ch), qlp + src);
    }
    CPC();
    kv_issue(sb, 0, 0, khp, vhp, tid); CPC();
    kv_issue(sb, 1, 1, khp, vhp, tid); CPC();

    // mask2 row -> smem (x itemp), once
    float* m2s = (float*)(sm + F_M2);
    for (int i = tid; i < NN / 4; i += 256) {
        float4 f = *(const float4*)(mask2 + b * NN + i * 4);
        float4 gg = { f.x * itemp, f.y * itemp, f.z * itemp, f.w * itemp };
        *(float4*)(m2s + i * 4) = gg;
    }

    CPW(2);            // Q arrived
    __syncthreads();

    uint32_t qh[4][4], ql[4][4];
#pragma unroll
    for (int ks = 0; ks < 4; ks++) {
        ldsm4(sb + F_QH + AOFF(wm * 16 + lr, ks * 2 + lc), qh[ks]);
        ldsm4(sb + F_QL + AOFF(wm * 16 + lr, ks * 2 + lc), ql[ks]);
    }

    const float m1r0 = mask1[b * NN + mt * 64 + wm * 16 + g] * itemp;
    const float m1r1 = mask1[b * NN + mt * 64 + wm * 16 + 8 + g] * itemp;

    float o[8][4];
#pragma unroll
    for (int j = 0; j < 8; j++)
#pragma unroll
        for (int c = 0; c < 4; c++) o[j][c] = 0.f;
    float mst0 = -1e30f, mst1 = -1e30f, l0 = 0.f, l1 = 0.f;

    float* red = (float*)(sm + F_RED);
    const int r0 = wm * 16 + g;

    for (int it = 0; it < NN / 64; it++) {
        if (it + 1 < NN / 64) { CPW(1); } else { CPW(0); }
        __syncthreads();
        const uint32_t skv = sb + F_KV + (it & 1) * FSTG;

        // ---- S = Qh*Kh + Ql*Kh ----
        float s[4][4];
#pragma unroll
        for (int j = 0; j < 4; j++)
#pragma unroll
            for (int c = 0; c < 4; c++) s[j][c] = 0.f;
#pragma unroll
        for (int ks = 0; ks < 4; ks++) {
            const int chk = ks * 2 + lc;
            uint32_t bhf[4][2];
#pragma unroll
            for (int jj = 0; jj < 2; jj++) {
                uint32_t q[4];
                ldsm4(skv + AOFF(wn * 32 + jj * 16 + lr, chk), q);
                bhf[jj * 2][0] = q[0]; bhf[jj * 2][1] = q[2];
                bhf[jj * 2 + 1][0] = q[1]; bhf[jj * 2 + 1][1] = q[3];
            }
#pragma unroll
            for (int j = 0; j < 4; j++) {
                mma_hf(s[j], qh[ks], bhf[j]);
                mma_hf(s[j], ql[ks], bhf[j]);
            }
        }

        // ---- bias + WARP-LOCAL row max over this half's 32 cols ----
        float mx0 = -1e30f, mx1 = -1e30f;
#pragma unroll
        for (int j = 0; j < 4; j++) {
            float2 mm = *(float2*)(m2s + it * 64 + wn * 32 + j * 8 + t * 2);
            s[j][0] = s[j][0] + m1r0 - mm.x;
            s[j][1] = s[j][1] + m1r0 - mm.y;
            s[j][2] = s[j][2] + m1r1 - mm.x;
            s[j][3] = s[j][3] + m1r1 - mm.y;
            mx0 = fmaxf(mx0, fmaxf(s[j][0], s[j][1]));
            mx1 = fmaxf(mx1, fmaxf(s[j][2], s[j][3]));
        }
        mx0 = fmaxf(mx0, __shfl_xor_sync(0xffffffffu, mx0, 1));
        mx0 = fmaxf(mx0, __shfl_xor_sync(0xffffffffu, mx0, 2));
        mx1 = fmaxf(mx1, __shfl_xor_sync(0xffffffffu, mx1, 1));
        mx1 = fmaxf(mx1, __shfl_xor_sync(0xffffffffu, mx1, 2));

        float mn0 = fmaxf(mst0, mx0), mn1 = fmaxf(mst1, mx1);
        float c0 = __expf(mst0 - mn0), c1 = __expf(mst1 - mn1);
        mst0 = mn0; mst1 = mn1;

        float rs0 = 0.f, rs1 = 0.f;
#pragma unroll
        for (int j = 0; j < 4; j++) {
            s[j][0] = __expf(s[j][0] - mn0);
            s[j][1] = __expf(s[j][1] - mn0);
            s[j][2] = __expf(s[j][2] - mn1);
            s[j][3] = __expf(s[j][3] - mn1);
            rs0 += s[j][0] + s[j][1];
            rs1 += s[j][2] + s[j][3];
        }
        rs0 += __shfl_xor_sync(0xffffffffu, rs0, 1);
        rs0 += __shfl_xor_sync(0xffffffffu, rs0, 2);
        rs1 += __shfl_xor_sync(0xffffffffu, rs1, 1);
        rs1 += __shfl_xor_sync(0xffffffffu, rs1, 2);
        l0 = l0 * c0 + rs0;
        l1 = l1 * c1 + rs1;
#pragma unroll
        for (int j = 0; j < 8; j++) {
            o[j][0] *= c0; o[j][1] *= c0;
            o[j][2] *= c1; o[j][3] *= c1;
        }

        // ---- O += Ph*Vh + Pl*Vh (P split from regs) ----
#pragma unroll
        for (int kks = 0; kks < 2; kks++) {
            const int j0 = 2 * kks, j1 = j0 + 1;
            uint32_t pah[4], pal[4];
            pah[0] = pkh(s[j0][0], s[j0][1]);
            pah[1] = pkh(s[j0][2], s[j0][3]);
            pah[2] = pkh(s[j1][0], s[j1][1]);
            pah[3] = pkh(s[j1][2], s[j1][3]);
            pal[0] = pkh(s[j0][0] - lofH(pah[0]), s[j0][1] - hifH(pah[0]));
            pal[1] = pkh(s[j0][2] - lofH(pah[1]), s[j0][3] - hifH(pah[1]));
            pal[2] = pkh(s[j1][0] - lofH(pah[2]), s[j1][1] - hifH(pah[2]));
            pal[3] = pkh(s[j1][2] - lofH(pah[3]), s[j1][3] - hifH(pah[3]));

            uint32_t vhf[8][2];
#pragma unroll
            for (int jj = 0; jj < 4; jj++) {
                uint32_t q[4];
                ldsm4t(skv + 8192 + AOFF(wn * 32 + kks * 16 + lr, jj * 2 + lc), q);
                vhf[jj * 2][0] = q[0]; vhf[jj * 2][1] = q[1];
                vhf[jj * 2 + 1][0] = q[2]; vhf[jj * 2 + 1][1] = q[3];
            }
#pragma unroll
            for (int j = 0; j < 8; j++) {
                mma_hf(o[j], pah, vhf[j]);
                mma_hf(o[j], pal, vhf[j]);
            }
        }

        __syncthreads();
        if (it + 2 < NN / 64) {
            kv_issue(sb, it & 1, it + 2, khp, vhp, tid); CPC();
        }
    }

    // ---- epilogue: merge the two independent softmax halves, store --------
    __syncthreads();
    float* ob = (float*)(sm + F_OB);
    if (wn == 1) {
#pragma unroll
        for (int j = 0; j < 8; j++) {
            *(float2*)(ob + r0 * 68 + j * 8 + t * 2) = make_float2(o[j][0], o[j][1]);
            *(float2*)(ob + (r0 + 8) * 68 + j * 8 + t * 2) = make_float2(o[j][2], o[j][3]);
        }
        if (t == 0) {
            red[r0]      = l0;   red[r0 + 8]      = l1;
            red[64 + r0] = mst0; red[64 + r0 + 8] = mst1;
        }
    }
    __syncthreads();
    if (wn == 0) {
        float mB0 = red[64 + r0], mB1 = red[64 + r0 + 8];
        float lB0 = red[r0],      lB1 = red[r0 + 8];
        float m0f = fmaxf(mst0, mB0), m1f = fmaxf(mst1, mB1);
        float cA0 = __expf(mst0 - m0f), cB0 = __expf(mB0 - m0f);
        float cA1 = __expf(mst1 - m1f), cB1 = __expf(mB1 - m1f);
        float inv0 = 1.0f / (l0 * cA0 + lB0 * cB0);
        float inv1 = 1.0f / (l1 * cA1 + lB1 * cB1);
#pragma unroll
        for (int j = 0; j < 8; j++) {
            float2 u0 = *(float2*)(ob + r0 * 68 + j * 8 + t * 2);
            float2 u1 = *(float2*)(ob + (r0 + 8) * 68 + j * 8 + t * 2);
            float2 w0 = make_float2((o[j][0] * cA0 + u0.x * cB0) * inv0,
                                    (o[j][1] * cA0 + u0.y * cB0) * inv0);
            float2 w1 = make_float2((o[j][2] * cA1 + u1.x * cB1) * inv1,
                                    (o[j][3] * cA1 + u1.y * cB1) * inv1);
            size_t i0 = (size_t)(b * NN + mt * 64 + r0) * 384 + h * 32 + j * 4 + t;
            size_t i1 = (size_t)(b * NN + mt * 64 + r0 + 8) * 384 + h * 32 + j * 4 + t;
            uint32_t h0 = pkh(w0.x, w0.y);
            uint32_t l0u = pkh(w0.x - lofH(h0), w0.y - hifH(h0));
            uint32_t h1 = pkh(w1.x, w1.y);
            uint32_t l1u = pkh(w1.x - lofH(h1), w1.y - hifH(h1));
            g_aoh[i0] = h0; g_aol[i0] = l0u;
            g_aoh[i1] = h1; g_aol[i1] = l1u;
        }
    }
}

// ---------------------------------------------------------------------------
// LayerNorm(0.5*x1 + g_t)
// ---------------------------------------------------------------------------
__global__ __launch_bounds__(256) void ln_kernel(
    const float* __restrict__ x1, const float* __restrict__ gamma,
    const float* __restrict__ beta, float* __restrict__ out)
{
    const int row = blockIdx.x;
    const int tid = threadIdx.x;
    const float* tr = g_t + (size_t)row * NC;
    const float* xr = x1 + (size_t)row * NC;

    float z[3];
    float s = 0.f;
#pragma unroll
    for (int u = 0; u < 3; u++) {
        int idx = tid + u * 256;
        z[u] = 0.5f * xr[idx] + tr[idx];
        s += z[u];
    }

    __shared__ float red[8];
#pragma unroll
    for (int off = 16; off >= 1; off >>= 1) s += __shfl_xor_sync(0xffffffffu, s, off);
    if ((tid & 31) == 0) red[tid >> 5] = s;
    __syncthreads();
    float tot = 0.f;
#pragma unroll
    for (int w = 0; w < 8; w++) tot += red[w];
    const float mu = tot * (1.0f / NC);

    float s2 = 0.f;
#pragma unroll
    for (int u = 0; u < 3; u++) {
        float d = z[u] - mu;
        s2 += d * d;
    }
    __syncthreads();
#pragma unroll
    for (int off = 16; off >= 1; off >>= 1) s2 += __shfl_xor_sync(0xffffffffu, s2, off);
    if ((tid & 31) == 0) red[tid >> 5] = s2;
    __syncthreads();
    float tot2 = 0.f;
#pragma unroll
    for (int w = 0; w < 8; w++) tot2 += red[w];
    const float rstd = rsqrtf(tot2 * (1.0f / NC) + 1e-5f);

    float* orow = out + (size_t)row * NC;
#pragma unroll
    for (int u = 0; u < 3; u++) {
        int idx = tid + u * 256;
        orow[idx] = (z[u] - mu) * rstd * gamma[idx] + beta[idx];
    }
}

// ---------------------------------------------------------------------------
extern "C" void kernel_launch(void* const* d_in, const int* in_sizes, int n_in,
                              void* d_out, int out_size)
{
    (void)in_sizes; (void)n_in; (void)out_size;
    const float* x1    = (const float*)d_in[0];
    const float* x2    = (const float*)d_in[1];
    const float* mask1 = (const float*)d_in[2];
    const float* mask2 = (const float*)d_in[3];
    const float* Wq    = (const float*)d_in[4];
    const float* bq    = (const float*)d_in[5];
    const float* Wk    = (const float*)d_in[6];
    const float* bk    = (const float*)d_in[7];
    const float* Wv    = (const float*)d_in[8];
    const float* bv    = (const float*)d_in[9];
    const float* Wo    = (const float*)d_in[10];
    const float* bo    = (const float*)d_in[11];
    const float* temp  = (const float*)d_in[12];
    const float* gamma = (const float*)d_in[13];
    const float* beta  = (const float*)d_in[14];
    float* out = (float*)d_out;

    cudaFuncSetAttribute(mma_flash2,
                         cudaFuncAttributeMaxDynamicSharedMemorySize, ATT_SMEM);
    cudaFuncSetAttribute(mma_gemm2,
                         cudaFuncAttributeMaxDynamicSharedMemorySize, GEMM_SMEM);

    // prep: fused fp32 -> fp16 split (single launch)
    split_all<<<(TOT4 + 255) / 256, 256>>>(x1, x2, Wq, Wk, Wv, Wo);

    // QKV projections
    mma_gemm2<<<dim3(NC / 128, (NB * NN) / 128, 3), 256, GEMM_SMEM>>>(bq, bk, bv, bo, 0);
    // attention
    mma_flash2<<<dim3(NN / 64, NB * NH), 256, ATT_SMEM>>>(mask1, mask2, temp);
    // output projection
    mma_gemm2<<<dim3(NC / 128, (NB * NN) / 128, 1), 256, GEMM_SMEM>>>(bq, bk, bv, bo, 1);
    ln_kernel<<<NB * NN, 256>>>(x1, gamma, beta, out);
}

// round 12
// speedup vs baseline: 1.6505x; 1.1563x over previous
#include <cuda_runtime.h>
#include <cstdint>

#define NB 4
#define NN 2048
#define NC 768
#define NH 12
#define ND 64
#define WPAIR (NC * NC / 2)        // 294912 uint32 pairs per weight matrix
#define XPAIR (NB * NN * NC / 2)   // 3145728
#define QPAIR (NB * NH * NN * ND / 2)

// ---------------- scratch (device globals; no allocation allowed) ----------
__device__ uint32_t g_wh[4 * WPAIR];                     // weights: fp16 hi only (B side)
__device__ uint32_t g_x1h[XPAIR], g_x1l[XPAIR];          // activations: fp16 hi+lo (A side)
__device__ uint32_t g_x2h[XPAIR], g_x2l[XPAIR];
__device__ uint32_t g_qh[QPAIR];                         // Q: hi only (x0.125)
__device__ uint32_t g_kh[QPAIR];                         // K: hi only
__device__ uint32_t g_vh[QPAIR];                         // V: hi only
__device__ uint32_t g_aoh[XPAIR], g_aol[XPAIR];          // attention out: hi+lo (A side)
__device__ float    g_t[NB * NN * NC];                   // oproj out (fp32 for LN)

// ======================= helpers (sm_80-level PTX only) =====================
static __device__ __forceinline__ uint32_t smem_u32(const void* p) {
    uint32_t a;
    asm("{ .reg .u64 t; cvta.to.shared.u64 t, %1; cvt.u32.u64 %0, t; }"
        : "=r"(a) : "l"(p));
    return a;
}
// pack two fp32 -> fp16x2 (lo in low half)
static __device__ __forceinline__ uint32_t pkh(float lo, float hi) {
    uint32_t r;
    asm("cvt.rn.f16x2.f32 %0, %1, %2;" : "=r"(r) : "f"(hi), "f"(lo));
    return r;
}
static __device__ __forceinline__ float lofH(uint32_t u) {
    float f;
    asm("{ .reg .b16 l, h; mov.b32 {l, h}, %1; cvt.f32.f16 %0, l; }"
        : "=f"(f) : "r"(u));
    return f;
}
static __device__ __forceinline__ float hifH(uint32_t u) {
    float f;
    asm("{ .reg .b16 l, h; mov.b32 {l, h}, %1; cvt.f32.f16 %0, h; }"
        : "=f"(f) : "r"(u));
    return f;
}
static __device__ __forceinline__ void ldsm4(uint32_t a, uint32_t* r) {
    asm volatile("ldmatrix.sync.aligned.m8n8.x4.shared.b16 {%0,%1,%2,%3}, [%4];"
                 : "=r"(r[0]), "=r"(r[1]), "=r"(r[2]), "=r"(r[3]) : "r"(a));
}
static __device__ __forceinline__ void ldsm4t(uint32_t a, uint32_t* r) {
    asm volatile("ldmatrix.sync.aligned.m8n8.x4.trans.shared.b16 {%0,%1,%2,%3}, [%4];"
                 : "=r"(r[0]), "=r"(r[1]), "=r"(r[2]), "=r"(r[3]) : "r"(a));
}
static __device__ __forceinline__ void mma_hf(float* c, const uint32_t* a, const uint32_t* b) {
    asm volatile("mma.sync.aligned.m16n8k16.row.col.f32.f16.f16.f32 "
                 "{%0,%1,%2,%3},{%4,%5,%6,%7},{%8,%9},{%0,%1,%2,%3};"
                 : "+f"(c[0]), "+f"(c[1]), "+f"(c[2]), "+f"(c[3])
                 : "r"(a[0]), "r"(a[1]), "r"(a[2]), "r"(a[3]),
                   "r"(b[0]), "r"(b[1]));
}
#define CPA(dst, src) \
    asm volatile("cp.async.cg.shared.global [%0], [%1], 16;" :: "r"(dst), "l"(src))
#define CPC() asm volatile("cp.async.commit_group;" ::: "memory")
#define CPW(n) asm volatile("cp.async.wait_group %0;" :: "n"(n) : "memory")

// swizzled smem byte offsets (16B granules, conflict-free ldmatrix)
#define GOFF(r, ch) ((((r) >> 1) * 128) + ((((((r) & 1) << 2) | (ch)) ^ (((r) >> 1) & 7)) * 16))
#define AOFF(r, ch) (((r) * 128) + ((((ch) ^ ((r) & 7))) * 16))

// ======================= prep: fused fp32 -> fp16 split =====================
#define XN4 (NB * NN * NC / 4)
#define WN4 (NC * NC / 4)
#define TOT4 (2 * XN4 + 4 * WN4)

__global__ __launch_bounds__(256) void split_all(
    const float* __restrict__ x1, const float* __restrict__ x2,
    const float* __restrict__ Wq, const float* __restrict__ Wk,
    const float* __restrict__ Wv, const float* __restrict__ Wo)
{
    int i = blockIdx.x * blockDim.x + threadIdx.x;
    if (i >= TOT4) return;
    if (i < 2 * XN4) {
        const float* src = (i < XN4) ? x1 : x2;
        uint32_t* dh = (i < XN4) ? g_x1h : g_x2h;
        uint32_t* dl = (i < XN4) ? g_x1l : g_x2l;
        int li = (i < XN4) ? i : i - XN4;
        float4 f = ((const float4*)src)[li];
        uint32_t h0 = pkh(f.x, f.y), h1 = pkh(f.z, f.w);
        uint32_t l0 = pkh(f.x - lofH(h0), f.y - hifH(h0));
        uint32_t l1 = pkh(f.z - lofH(h1), f.w - hifH(h1));
        ((uint2*)dh)[li] = make_uint2(h0, h1);
        ((uint2*)dl)[li] = make_uint2(l0, l1);
    } else {
        int j = i - 2 * XN4;
        int w = j / WN4;
        int li = j - w * WN4;
        const float* src = (w == 0) ? Wq : (w == 1) ? Wk : (w == 2) ? Wv : Wo;
        uint32_t* dh = g_wh + (size_t)w * WPAIR;
        float4 f = ((const float4*)src)[li];
        ((uint2*)dh)[li] = make_uint2(pkh(f.x, f.y), pkh(f.z, f.w));
    }
}

// ======================= fp16 2-term mma GEMM ================================
// C[M,768] = A @ W^T + bias; D = Ah*Wh + Al*Wh (W hi only).
// CTA 128x128, BK=32, 8 warps (4M x 2N). 2-stage cp.async.
#define GSTG 24576
#define GEMM_SMEM (2 * GSTG)      // 49152

static __device__ __forceinline__ void gemm_issue(
    uint32_t sb, int buf, int c, const uint32_t* Ah, const uint32_t* Al,
    const uint32_t* Wh, int m0, int n0, int tid)
{
#pragma unroll
    for (int p = 0; p < 2; p++) {
        int cid = tid + p * 256;
        int r = cid >> 2, ch = cid & 3;
        size_t sa = (size_t)(m0 + r) * 384 + c * 16 + ch * 4;
        size_t sw = (size_t)(n0 + r) * 384 + c * 16 + ch * 4;
        uint32_t d = sb + buf * GSTG + GOFF(r, ch);
        CPA(d,         Ah + sa);
        CPA(d + 8192,  Al + sa);
        CPA(d + 16384, Wh + sw);
    }
}

__global__ __launch_bounds__(256) void mma_gemm2(
    const float* __restrict__ bq, const float* __restrict__ bk,
    const float* __restrict__ bv, const float* __restrict__ bo, int phase)
{
    extern __shared__ __align__(128) char gsm[];
    const uint32_t sb = smem_u32(gsm);
    const int mode = phase ? 3 : (int)blockIdx.z;
    const uint32_t* Ah = (mode == 0) ? g_x1h : (mode == 3) ? g_aoh : g_x2h;
    const uint32_t* Al = (mode == 0) ? g_x1l : (mode == 3) ? g_aol : g_x2l;
    const uint32_t* Wh = g_wh + (size_t)mode * WPAIR;
    const float* bias = (mode == 0) ? bq : (mode == 1) ? bk : (mode == 2) ? bv : bo;

    const int n0 = blockIdx.x * 128;
    const int m0 = blockIdx.y * 128;
    const int tid  = threadIdx.x;
    const int lane = tid & 31;
    const int wid  = tid >> 5;
    const int wm = wid & 3;
    const int wn = wid >> 2;
    const int g  = lane >> 2;
    const int t  = lane & 3;
    const int lr = lane & 15;
    const int lc = lane >> 4;

    float acc[2][8][4];
#pragma unroll
    for (int i = 0; i < 2; i++)
#pragma unroll
        for (int j = 0; j < 8; j++)
#pragma unroll
            for (int c = 0; c < 4; c++) acc[i][j][c] = 0.f;

    gemm_issue(sb, 0, 0, Ah, Al, Wh, m0, n0, tid); CPC();
    gemm_issue(sb, 1, 1, Ah, Al, Wh, m0, n0, tid); CPC();

    for (int c = 0; c < NC / 32; c++) {
        if (c + 1 < NC / 32) { CPW(1); } else { CPW(0); }
        __syncthreads();
        const uint32_t s2 = sb + (c & 1) * GSTG;

#pragma unroll
        for (int ks = 0; ks < 2; ks++) {
            const int chk = ks * 2 + lc;
            uint32_t ah[2][4], al[2][4], bh[8][2];
#pragma unroll
            for (int mf = 0; mf < 2; mf++) {
                ldsm4(s2 + GOFF(wm * 32 + mf * 16 + lr, chk), ah[mf]);
                ldsm4(s2 + 8192 + GOFF(wm * 32 + mf * 16 + lr, chk), al[mf]);
            }
#pragma unroll
            for (int jj = 0; jj < 4; jj++) {
                uint32_t q[4];
                ldsm4(s2 + 16384 + GOFF(wn * 64 + jj * 16 + lr, chk), q);
                bh[jj * 2][0] = q[0]; bh[jj * 2][1] = q[2];
                bh[jj * 2 + 1][0] = q[1]; bh[jj * 2 + 1][1] = q[3];
            }
#pragma unroll
            for (int mf = 0; mf < 2; mf++)
#pragma unroll
                for (int j = 0; j < 8; j++) {
                    mma_hf(acc[mf][j], ah[mf], bh[j]);
                    mma_hf(acc[mf][j], al[mf], bh[j]);
                }
        }
        __syncthreads();
        if (c + 2 < NC / 32) {
            gemm_issue(sb, c & 1, c + 2, Ah, Al, Wh, m0, n0, tid); CPC();
        }
    }

#pragma unroll
    for (int mf = 0; mf < 2; mf++) {
        int r = m0 + wm * 32 + mf * 16 + g;
#pragma unroll
        for (int j = 0; j < 8; j++) {
            int cg = n0 + wn * 64 + j * 8 + t * 2;
            float bx = bias[cg], by = bias[cg + 1];
            float2 v0 = { acc[mf][j][0] + bx, acc[mf][j][1] + by };
            float2 v1 = { acc[mf][j][2] + bx, acc[mf][j][3] + by };
            if (mode == 3) {
                *(float2*)(g_t + (size_t)r * NC + cg) = v0;
                *(float2*)(g_t + (size_t)(r + 8) * NC + cg) = v1;
            } else {
                int b = r >> 11, h = cg >> 6, dp = (cg & 63) >> 1;
                size_t base = ((size_t)(b * NH + h)) * NN;
                size_t i0 = (base + (r & (NN - 1))) * 32 + dp;
                size_t i1 = (base + ((r + 8) & (NN - 1))) * 32 + dp;
                if (mode == 0) {
                    v0.x *= 0.125f; v0.y *= 0.125f;
                    v1.x *= 0.125f; v1.y *= 0.125f;
                    g_qh[i0] = pkh(v0.x, v0.y);
                    g_qh[i1] = pkh(v1.x, v1.y);
                } else {
                    uint32_t* dst = (mode == 1) ? g_kh : g_vh;
                    dst[i0] = pkh(v0.x, v0.y);
                    dst[i1] = pkh(v1.x, v1.y);
                }
            }
        }
    }
}

// ======================= pure-fp16 mma flash attention =======================
// CTA 64 Q-rows; 8 warps 4(M)x2(N). Independent per-half online softmax,
// merged once in epilogue. S = Qh*Kh; O += Ph*Vh. (1-term fp16)
// smem: m2 8K | red 512 | Qhi 8K | KV stages 2x16K (Kh|Vh)
#define F_M2  0
#define F_RED 8192
#define F_QH  8704
#define F_KV  16896
#define F_OB  16896                       // aliases KV (used only after loop)
#define FSTG  16384
#define ATT_SMEM (F_KV + 2 * FSTG)        // 49664

static __device__ __forceinline__ void kv_issue(
    uint32_t sb, int buf, int it, const uint32_t* kh, const uint32_t* vh, int tid)
{
#pragma unroll
    for (int p = 0; p < 2; p++) {
        int cid = tid + p * 256;
        int r = cid >> 3, ch = cid & 7;
        size_t src = (size_t)(it * 64 + r) * 32 + ch * 4;
        uint32_t d = sb + F_KV + buf * FSTG + AOFF(r, ch);
        CPA(d,         kh + src);
        CPA(d + 8192,  vh + src);
    }
}

__global__ __launch_bounds__(256) void mma_flash2(
    const float* __restrict__ mask1, const float* __restrict__ mask2,
    const float* __restrict__ temp_p)
{
    extern __shared__ __align__(128) char sm[];
    const uint32_t sb = smem_u32(sm);
    const int mt = blockIdx.x;
    const int bh = blockIdx.y;
    const int b  = bh / NH;
    const int h  = bh % NH;
    const int tid  = threadIdx.x;
    const int lane = tid & 31;
    const int wid  = tid >> 5;
    const int wm = wid & 3;
    const int wn = wid >> 2;
    const int g  = lane >> 2;
    const int t  = lane & 3;
    const int lr = lane & 15;
    const int lc = lane >> 4;

    const float itemp = 1.0f / temp_p[0];

    const uint32_t* qhp = g_qh + ((size_t)bh * NN + mt * 64) * 32;
    const uint32_t* khp = g_kh + (size_t)bh * NN * 32;
    const uint32_t* vhp = g_vh + (size_t)bh * NN * 32;

    // Q tile (group 0)
    {
        int cid = tid;
        int r = cid >> 2, ch = (cid & 3) << 1;   // 256 threads x 2 chunks each
        size_t src = (size_t)r * 32 + ch * 4;
        CPA(sb + F_QH + AOFF(r, ch),     qhp + src);
        CPA(sb + F_QH + AOFF(r, ch + 1), qhp + src + 4);
    }
    CPC();
    kv_issue(sb, 0, 0, khp, vhp, tid); CPC();
    kv_issue(sb, 1, 1, khp, vhp, tid); CPC();

    // mask2 row -> smem (x itemp), once
    float* m2s = (float*)(sm + F_M2);
    for (int i = tid; i < NN / 4; i += 256) {
        float4 f = *(const float4*)(mask2 + b * NN + i * 4);
        float4 gg = { f.x * itemp, f.y * itemp, f.z * itemp, f.w * itemp };
        *(float4*)(m2s + i * 4) = gg;
    }

    CPW(2);            // Q arrived
    __syncthreads();

    uint32_t qh[4][4];
#pragma unroll
    for (int ks = 0; ks < 4; ks++)
        ldsm4(sb + F_QH + AOFF(wm * 16 + lr, ks * 2 + lc), qh[ks]);

    const float m1r0 = mask1[b * NN + mt * 64 + wm * 16 + g] * itemp;
    const float m1r1 = mask1[b * NN + mt * 64 + wm * 16 + 8 + g] * itemp;

    float o[8][4];
#pragma unroll
    for (int j = 0; j < 8; j++)
#pragma unroll
        for (int c = 0; c < 4; c++) o[j][c] = 0.f;
    float mst0 = -1e30f, mst1 = -1e30f, l0 = 0.f, l1 = 0.f;

    float* red = (float*)(sm + F_RED);
    const int r0 = wm * 16 + g;

    for (int it = 0; it < NN / 64; it++) {
        if (it + 1 < NN / 64) { CPW(1); } else { CPW(0); }
        __syncthreads();
        const uint32_t skv = sb + F_KV + (it & 1) * FSTG;

        // ---- S = Qh*Kh ----
        float s[4][4];
#pragma unroll
        for (int j = 0; j < 4; j++)
#pragma unroll
            for (int c = 0; c < 4; c++) s[j][c] = 0.f;
#pragma unroll
        for (int ks = 0; ks < 4; ks++) {
            const int chk = ks * 2 + lc;
            uint32_t bhf[4][2];
#pragma unroll
            for (int jj = 0; jj < 2; jj++) {
                uint32_t q[4];
                ldsm4(skv + AOFF(wn * 32 + jj * 16 + lr, chk), q);
                bhf[jj * 2][0] = q[0]; bhf[jj * 2][1] = q[2];
                bhf[jj * 2 + 1][0] = q[1]; bhf[jj * 2 + 1][1] = q[3];
            }
#pragma unroll
            for (int j = 0; j < 4; j++)
                mma_hf(s[j], qh[ks], bhf[j]);
        }

        // ---- bias + WARP-LOCAL row max over this half's 32 cols ----
        float mx0 = -1e30f, mx1 = -1e30f;
#pragma unroll
        for (int j = 0; j < 4; j++) {
            float2 mm = *(float2*)(m2s + it * 64 + wn * 32 + j * 8 + t * 2);
            s[j][0] = s[j][0] + m1r0 - mm.x;
            s[j][1] = s[j][1] + m1r0 - mm.y;
            s[j][2] = s[j][2] + m1r1 - mm.x;
            s[j][3] = s[j][3] + m1r1 - mm.y;
            mx0 = fmaxf(mx0, fmaxf(s[j][0], s[j][1]));
            mx1 = fmaxf(mx1, fmaxf(s[j][2], s[j][3]));
        }
        mx0 = fmaxf(mx0, __shfl_xor_sync(0xffffffffu, mx0, 1));
        mx0 = fmaxf(mx0, __shfl_xor_sync(0xffffffffu, mx0, 2));
        mx1 = fmaxf(mx1, __shfl_xor_sync(0xffffffffu, mx1, 1));
        mx1 = fmaxf(mx1, __shfl_xor_sync(0xffffffffu, mx1, 2));

        float mn0 = fmaxf(mst0, mx0), mn1 = fmaxf(mst1, mx1);
        float c0 = __expf(mst0 - mn0), c1 = __expf(mst1 - mn1);
        mst0 = mn0; mst1 = mn1;

        float rs0 = 0.f, rs1 = 0.f;
#pragma unroll
        for (int j = 0; j < 4; j++) {
            s[j][0] = __expf(s[j][0] - mn0);
            s[j][1] = __expf(s[j][1] - mn0);
            s[j][2] = __expf(s[j][2] - mn1);
            s[j][3] = __expf(s[j][3] - mn1);
            rs0 += s[j][0] + s[j][1];
            rs1 += s[j][2] + s[j][3];
        }
        rs0 += __shfl_xor_sync(0xffffffffu, rs0, 1);
        rs0 += __shfl_xor_sync(0xffffffffu, rs0, 2);
        rs1 += __shfl_xor_sync(0xffffffffu, rs1, 1);
        rs1 += __shfl_xor_sync(0xffffffffu, rs1, 2);
        l0 = l0 * c0 + rs0;
        l1 = l1 * c1 + rs1;
#pragma unroll
        for (int j = 0; j < 8; j++) {
            o[j][0] *= c0; o[j][1] *= c0;
            o[j][2] *= c1; o[j][3] *= c1;
        }

        // ---- O += Ph*Vh (P from regs, hi only) ----
#pragma unroll
        for (int kks = 0; kks < 2; kks++) {
            const int j0 = 2 * kks, j1 = j0 + 1;
            uint32_t pah[4];
            pah[0] = pkh(s[j0][0], s[j0][1]);
            pah[1] = pkh(s[j0][2], s[j0][3]);
            pah[2] = pkh(s[j1][0], s[j1][1]);
            pah[3] = pkh(s[j1][2], s[j1][3]);

            uint32_t vhf[8][2];
#pragma unroll
            for (int jj = 0; jj < 4; jj++) {
                uint32_t q[4];
                ldsm4t(skv + 8192 + AOFF(wn * 32 + kks * 16 + lr, jj * 2 + lc), q);
                vhf[jj * 2][0] = q[0]; vhf[jj * 2][1] = q[1];
                vhf[jj * 2 + 1][0] = q[2]; vhf[jj * 2 + 1][1] = q[3];
            }
#pragma unroll
            for (int j = 0; j < 8; j++)
                mma_hf(o[j], pah, vhf[j]);
        }

        __syncthreads();
        if (it + 2 < NN / 64) {
            kv_issue(sb, it & 1, it + 2, khp, vhp, tid); CPC();
        }
    }

    // ---- epilogue: merge the two independent softmax halves, store --------
    __syncthreads();
    float* ob = (float*)(sm + F_OB);
    if (wn == 1) {
#pragma unroll
        for (int j = 0; j < 8; j++) {
            *(float2*)(ob + r0 * 68 + j * 8 + t * 2) = make_float2(o[j][0], o[j][1]);
            *(float2*)(ob + (r0 + 8) * 68 + j * 8 + t * 2) = make_float2(o[j][2], o[j][3]);
        }
        if (t == 0) {
            red[r0]      = l0;   red[r0 + 8]      = l1;
            red[64 + r0] = mst0; red[64 + r0 + 8] = mst1;
        }
    }
    __syncthreads();
    if (wn == 0) {
        float mB0 = red[64 + r0], mB1 = red[64 + r0 + 8];
        float lB0 = red[r0],      lB1 = red[r0 + 8];
        float m0f = fmaxf(mst0, mB0), m1f = fmaxf(mst1, mB1);
        float cA0 = __expf(mst0 - m0f), cB0 = __expf(mB0 - m0f);
        float cA1 = __expf(mst1 - m1f), cB1 = __expf(mB1 - m1f);
        float inv0 = 1.0f / (l0 * cA0 + lB0 * cB0);
        float inv1 = 1.0f / (l1 * cA1 + lB1 * cB1);
#pragma unroll
        for (int j = 0; j < 8; j++) {
            float2 u0 = *(float2*)(ob + r0 * 68 + j * 8 + t * 2);
            float2 u1 = *(float2*)(ob + (r0 + 8) * 68 + j * 8 + t * 2);
            float2 w0 = make_float2((o[j][0] * cA0 + u0.x * cB0) * inv0,
                                    (o[j][1] * cA0 + u0.y * cB0) * inv0);
            float2 w1 = make_float2((o[j][2] * cA1 + u1.x * cB1) * inv1,
                                    (o[j][3] * cA1 + u1.y * cB1) * inv1);
            size_t i0 = (size_t)(b * NN + mt * 64 + r0) * 384 + h * 32 + j * 4 + t;
            size_t i1 = (size_t)(b * NN + mt * 64 + r0 + 8) * 384 + h * 32 + j * 4 + t;
            uint32_t h0 = pkh(w0.x, w0.y);
            uint32_t l0u = pkh(w0.x - lofH(h0), w0.y - hifH(h0));
            uint32_t h1 = pkh(w1.x, w1.y);
            uint32_t l1u = pkh(w1.x - lofH(h1), w1.y - hifH(h1));
            g_aoh[i0] = h0; g_aol[i0] = l0u;
            g_aoh[i1] = h1; g_aol[i1] = l1u;
        }
    }
}

// ---------------------------------------------------------------------------
// LayerNorm(0.5*x1 + g_t)
// ---------------------------------------------------------------------------
__global__ __launch_bounds__(256) void ln_kernel(
    const float* __restrict__ x1, const float* __restrict__ gamma,
    const float* __restrict__ beta, float* __restrict__ out)
{
    const int row = blockIdx.x;
    const int tid = threadIdx.x;
    const float* tr = g_t + (size_t)row * NC;
    const float* xr = x1 + (size_t)row * NC;

    float z[3];
    float s = 0.f;
#pragma unroll
    for (int u = 0; u < 3; u++) {
        int idx = tid + u * 256;
        z[u] = 0.5f * xr[idx] + tr[idx];
        s += z[u];
    }

    __shared__ float red[8];
#pragma unroll
    for (int off = 16; off >= 1; off >>= 1) s += __shfl_xor_sync(0xffffffffu, s, off);
    if ((tid & 31) == 0) red[tid >> 5] = s;
    __syncthreads();
    float tot = 0.f;
#pragma unroll
    for (int w = 0; w < 8; w++) tot += red[w];
    const float mu = tot * (1.0f / NC);

    float s2 = 0.f;
#pragma unroll
    for (int u = 0; u < 3; u++) {
        float d = z[u] - mu;
        s2 += d * d;
    }
    __syncthreads();
#pragma unroll
    for (int off = 16; off >= 1; off >>= 1) s2 += __shfl_xor_sync(0xffffffffu, s2, off);
    if ((tid & 31) == 0) red[tid >> 5] = s2;
    __syncthreads();
    float tot2 = 0.f;
#pragma unroll
    for (int w = 0; w < 8; w++) tot2 += red[w];
    const float rstd = rsqrtf(tot2 * (1.0f / NC) + 1e-5f);

    float* orow = out + (size_t)row * NC;
#pragma unroll
    for (int u = 0; u < 3; u++) {
        int idx = tid + u * 256;
        orow[idx] = (z[u] - mu) * rstd * gamma[idx] + beta[idx];
    }
}

// ---------------------------------------------------------------------------
extern "C" void kernel_launch(void* const* d_in, const int* in_sizes, int n_in,
                              void* d_out, int out_size)
{
    (void)in_sizes; (void)n_in; (void)out_size;
    const float* x1    = (const float*)d_in[0];
    const float* x2    = (const float*)d_in[1];
    const float* mask1 = (const float*)d_in[2];
    const float* mask2 = (const float*)d_in[3];
    const float* Wq    = (const float*)d_in[4];
    const float* bq    = (const float*)d_in[5];
    const float* Wk    = (const float*)d_in[6];
    const float* bk    = (const float*)d_in[7];
    const float* Wv    = (const float*)d_in[8];
    const float* bv    = (const float*)d_in[9];
    const float* Wo    = (const float*)d_in[10];
    const float* bo    = (const float*)d_in[11];
    const float* temp  = (const float*)d_in[12];
    const float* gamma = (const float*)d_in[13];
    const float* beta  = (const float*)d_in[14];
    float* out = (float*)d_out;

    cudaFuncSetAttribute(mma_flash2,
                         cudaFuncAttributeMaxDynamicSharedMemorySize, ATT_SMEM);
    cudaFuncSetAttribute(mma_gemm2,
                         cudaFuncAttributeMaxDynamicSharedMemorySize, GEMM_SMEM);

    // prep: fused fp32 -> fp16 split (single launch)
    split_all<<<(TOT4 + 255) / 256, 256>>>(x1, x2, Wq, Wk, Wv, Wo);

    // QKV projections
    mma_gemm2<<<dim3(NC / 128, (NB * NN) / 128, 3), 256, GEMM_SMEM>>>(bq, bk, bv, bo, 0);
    // attention (pure fp16, 1-term)
    mma_flash2<<<dim3(NN / 64, NB * NH), 256, ATT_SMEM>>>(mask1, mask2, temp);
    // output projection
    mma_gemm2<<<dim3(NC / 128, (NB * NN) / 128, 1), 256, GEMM_SMEM>>>(bq, bk, bv, bo, 1);
    ln_kernel<<<NB * NN, 256>>>(x1, gamma, beta, out);
}

// round 13
// speedup vs baseline: 2.0077x; 1.2165x over previous
#include <cuda_runtime.h>
#include <cstdint>

#define NB 4
#define NN 2048
#define NC 768
#define NH 12
#define ND 64
#define WPAIR (NC * NC / 2)        // 294912 uint32 pairs per weight matrix
#define XPAIR (NB * NN * NC / 2)   // 3145728
#define QPAIR (NB * NH * NN * ND / 2)

// ---------------- scratch (device globals; no allocation allowed) ----------
__device__ uint32_t g_wh[4 * WPAIR];                     // weights: fp16 (B side)
__device__ uint32_t g_x1h[XPAIR];                        // activations: fp16 (A side)
__device__ uint32_t g_x2h[XPAIR];
__device__ uint32_t g_qh[QPAIR];                         // Q: fp16 (x0.125)
__device__ uint32_t g_kh[QPAIR];                         // K: fp16
__device__ uint32_t g_vh[QPAIR];                         // V: fp16
__device__ uint32_t g_aoh[XPAIR];                        // attention out: fp16
__device__ float    g_t[NB * NN * NC];                   // oproj out (fp32 for LN)

// ======================= helpers (sm_80-level PTX only) =====================
static __device__ __forceinline__ uint32_t smem_u32(const void* p) {
    uint32_t a;
    asm("{ .reg .u64 t; cvta.to.shared.u64 t, %1; cvt.u32.u64 %0, t; }"
        : "=r"(a) : "l"(p));
    return a;
}
// pack two fp32 -> fp16x2 (lo in low half)
static __device__ __forceinline__ uint32_t pkh(float lo, float hi) {
    uint32_t r;
    asm("cvt.rn.f16x2.f32 %0, %1, %2;" : "=r"(r) : "f"(hi), "f"(lo));
    return r;
}
static __device__ __forceinline__ void ldsm4(uint32_t a, uint32_t* r) {
    asm volatile("ldmatrix.sync.aligned.m8n8.x4.shared.b16 {%0,%1,%2,%3}, [%4];"
                 : "=r"(r[0]), "=r"(r[1]), "=r"(r[2]), "=r"(r[3]) : "r"(a));
}
static __device__ __forceinline__ void ldsm4t(uint32_t a, uint32_t* r) {
    asm volatile("ldmatrix.sync.aligned.m8n8.x4.trans.shared.b16 {%0,%1,%2,%3}, [%4];"
                 : "=r"(r[0]), "=r"(r[1]), "=r"(r[2]), "=r"(r[3]) : "r"(a));
}
static __device__ __forceinline__ void mma_hf(float* c, const uint32_t* a, const uint32_t* b) {
    asm volatile("mma.sync.aligned.m16n8k16.row.col.f32.f16.f16.f32 "
                 "{%0,%1,%2,%3},{%4,%5,%6,%7},{%8,%9},{%0,%1,%2,%3};"
                 : "+f"(c[0]), "+f"(c[1]), "+f"(c[2]), "+f"(c[3])
                 : "r"(a[0]), "r"(a[1]), "r"(a[2]), "r"(a[3]),
                   "r"(b[0]), "r"(b[1]));
}
#define CPA(dst, src) \
    asm volatile("cp.async.cg.shared.global [%0], [%1], 16;" :: "r"(dst), "l"(src))
#define CPC() asm volatile("cp.async.commit_group;" ::: "memory")
#define CPW(n) asm volatile("cp.async.wait_group %0;" :: "n"(n) : "memory")

// swizzled smem byte offsets (16B granules, conflict-free ldmatrix)
#define GOFF(r, ch) ((((r) >> 1) * 128) + ((((((r) & 1) << 2) | (ch)) ^ (((r) >> 1) & 7)) * 16))
#define AOFF(r, ch) (((r) * 128) + ((((ch) ^ ((r) & 7))) * 16))

// ======================= prep: fused fp32 -> fp16 convert ===================
#define XN4 (NB * NN * NC / 4)
#define WN4 (NC * NC / 4)
#define TOT4 (2 * XN4 + 4 * WN4)

__global__ __launch_bounds__(256) void split_all(
    const float* __restrict__ x1, const float* __restrict__ x2,
    const float* __restrict__ Wq, const float* __restrict__ Wk,
    const float* __restrict__ Wv, const float* __restrict__ Wo)
{
    int i = blockIdx.x * blockDim.x + threadIdx.x;
    if (i >= TOT4) return;
    const float* src; uint32_t* dh; int li;
    if (i < XN4)          { src = x1; dh = g_x1h; li = i; }
    else if (i < 2 * XN4) { src = x2; dh = g_x2h; li = i - XN4; }
    else {
        int j = i - 2 * XN4;
        int w = j / WN4;
        li = j - w * WN4;
        src = (w == 0) ? Wq : (w == 1) ? Wk : (w == 2) ? Wv : Wo;
        dh = g_wh + (size_t)w * WPAIR;
    }
    float4 f = ((const float4*)src)[li];
    ((uint2*)dh)[li] = make_uint2(pkh(f.x, f.y), pkh(f.z, f.w));
}

// ======================= pure-fp16 mma GEMM ==================================
// C[M,768] = A @ W^T + bias; D = Ah*Wh (1-term fp16).
// CTA 128x128, BK=32, 8 warps (4M x 2N). 2-stage cp.async.
// stage: Ahi 8K | Bhi 8K = 16KB; 2 stages = 32KB.
#define GSTG 16384
#define GEMM_SMEM (2 * GSTG)      // 32768

static __device__ __forceinline__ void gemm_issue(
    uint32_t sb, int buf, int c, const uint32_t* Ah,
    const uint32_t* Wh, int m0, int n0, int tid)
{
#pragma unroll
    for (int p = 0; p < 2; p++) {
        int cid = tid + p * 256;
        int r = cid >> 2, ch = cid & 3;
        size_t sa = (size_t)(m0 + r) * 384 + c * 16 + ch * 4;
        size_t sw = (size_t)(n0 + r) * 384 + c * 16 + ch * 4;
        uint32_t d = sb + buf * GSTG + GOFF(r, ch);
        CPA(d,        Ah + sa);
        CPA(d + 8192, Wh + sw);
    }
}

__global__ __launch_bounds__(256) void mma_gemm2(
    const float* __restrict__ bq, const float* __restrict__ bk,
    const float* __restrict__ bv, const float* __restrict__ bo, int phase)
{
    extern __shared__ __align__(128) char gsm[];
    const uint32_t sb = smem_u32(gsm);
    const int mode = phase ? 3 : (int)blockIdx.z;
    const uint32_t* Ah = (mode == 0) ? g_x1h : (mode == 3) ? g_aoh : g_x2h;
    const uint32_t* Wh = g_wh + (size_t)mode * WPAIR;
    const float* bias = (mode == 0) ? bq : (mode == 1) ? bk : (mode == 2) ? bv : bo;

    const int n0 = blockIdx.x * 128;
    const int m0 = blockIdx.y * 128;
    const int tid  = threadIdx.x;
    const int lane = tid & 31;
    const int wid  = tid >> 5;
    const int wm = wid & 3;
    const int wn = wid >> 2;
    const int g  = lane >> 2;
    const int t  = lane & 3;
    const int lr = lane & 15;
    const int lc = lane >> 4;

    float acc[2][8][4];
#pragma unroll
    for (int i = 0; i < 2; i++)
#pragma unroll
        for (int j = 0; j < 8; j++)
#pragma unroll
            for (int c = 0; c < 4; c++) acc[i][j][c] = 0.f;

    gemm_issue(sb, 0, 0, Ah, Wh, m0, n0, tid); CPC();
    gemm_issue(sb, 1, 1, Ah, Wh, m0, n0, tid); CPC();

    for (int c = 0; c < NC / 32; c++) {
        if (c + 1 < NC / 32) { CPW(1); } else { CPW(0); }
        __syncthreads();
        const uint32_t s2 = sb + (c & 1) * GSTG;

#pragma unroll
        for (int ks = 0; ks < 2; ks++) {
            const int chk = ks * 2 + lc;
            uint32_t ah[2][4], bh[8][2];
#pragma unroll
            for (int mf = 0; mf < 2; mf++)
                ldsm4(s2 + GOFF(wm * 32 + mf * 16 + lr, chk), ah[mf]);
#pragma unroll
            for (int jj = 0; jj < 4; jj++) {
                uint32_t q[4];
                ldsm4(s2 + 8192 + GOFF(wn * 64 + jj * 16 + lr, chk), q);
                bh[jj * 2][0] = q[0]; bh[jj * 2][1] = q[2];
                bh[jj * 2 + 1][0] = q[1]; bh[jj * 2 + 1][1] = q[3];
            }
#pragma unroll
            for (int mf = 0; mf < 2; mf++)
#pragma unroll
                for (int j = 0; j < 8; j++)
                    mma_hf(acc[mf][j], ah[mf], bh[j]);
        }
        __syncthreads();
        if (c + 2 < NC / 32) {
            gemm_issue(sb, c & 1, c + 2, Ah, Wh, m0, n0, tid); CPC();
        }
    }

#pragma unroll
    for (int mf = 0; mf < 2; mf++) {
        int r = m0 + wm * 32 + mf * 16 + g;
#pragma unroll
        for (int j = 0; j < 8; j++) {
            int cg = n0 + wn * 64 + j * 8 + t * 2;
            float bx = bias[cg], by = bias[cg + 1];
            float2 v0 = { acc[mf][j][0] + bx, acc[mf][j][1] + by };
            float2 v1 = { acc[mf][j][2] + bx, acc[mf][j][3] + by };
            if (mode == 3) {
                *(float2*)(g_t + (size_t)r * NC + cg) = v0;
                *(float2*)(g_t + (size_t)(r + 8) * NC + cg) = v1;
            } else {
                int b = r >> 11, h = cg >> 6, dp = (cg & 63) >> 1;
                size_t base = ((size_t)(b * NH + h)) * NN;
                size_t i0 = (base + (r & (NN - 1))) * 32 + dp;
                size_t i1 = (base + ((r + 8) & (NN - 1))) * 32 + dp;
                if (mode == 0) {
                    v0.x *= 0.125f; v0.y *= 0.125f;
                    v1.x *= 0.125f; v1.y *= 0.125f;
                    g_qh[i0] = pkh(v0.x, v0.y);
                    g_qh[i1] = pkh(v1.x, v1.y);
                } else {
                    uint32_t* dst = (mode == 1) ? g_kh : g_vh;
                    dst[i0] = pkh(v0.x, v0.y);
                    dst[i1] = pkh(v1.x, v1.y);
                }
            }
        }
    }
}

// ======================= pure-fp16 mma flash attention =======================
// CTA 64 Q-rows; 8 warps 4(M)x2(N). Independent per-half online softmax,
// merged once in epilogue. S = Qh*Kh; O += Ph*Vh.
// smem: m2 8K | red 512 | Qhi 8K | KV stages 2x16K (Kh|Vh)
#define F_M2  0
#define F_RED 8192
#define F_QH  8704
#define F_KV  16896
#define F_OB  16896                       // aliases KV (used only after loop)
#define FSTG  16384
#define ATT_SMEM (F_KV + 2 * FSTG)        // 49664

static __device__ __forceinline__ void kv_issue(
    uint32_t sb, int buf, int it, const uint32_t* kh, const uint32_t* vh, int tid)
{
#pragma unroll
    for (int p = 0; p < 2; p++) {
        int cid = tid + p * 256;
        int r = cid >> 3, ch = cid & 7;
        size_t src = (size_t)(it * 64 + r) * 32 + ch * 4;
        uint32_t d = sb + F_KV + buf * FSTG + AOFF(r, ch);
        CPA(d,         kh + src);
        CPA(d + 8192,  vh + src);
    }
}

__global__ __launch_bounds__(256) void mma_flash2(
    const float* __restrict__ mask1, const float* __restrict__ mask2,
    const float* __restrict__ temp_p)
{
    extern __shared__ __align__(128) char sm[];
    const uint32_t sb = smem_u32(sm);
    const int mt = blockIdx.x;
    const int bh = blockIdx.y;
    const int b  = bh / NH;
    const int h  = bh % NH;
    const int tid  = threadIdx.x;
    const int lane = tid & 31;
    const int wid  = tid >> 5;
    const int wm = wid & 3;
    const int wn = wid >> 2;
    const int g  = lane >> 2;
    const int t  = lane & 3;
    const int lr = lane & 15;
    const int lc = lane >> 4;

    const float itemp = 1.0f / temp_p[0];

    const uint32_t* qhp = g_qh + ((size_t)bh * NN + mt * 64) * 32;
    const uint32_t* khp = g_kh + (size_t)bh * NN * 32;
    const uint32_t* vhp = g_vh + (size_t)bh * NN * 32;

    // Q tile (group 0)
    {
        int cid = tid;
        int r = cid >> 2, ch = (cid & 3) << 1;
        size_t src = (size_t)r * 32 + ch * 4;
        CPA(sb + F_QH + AOFF(r, ch),     qhp + src);
        CPA(sb + F_QH + AOFF(r, ch + 1), qhp + src + 4);
    }
    CPC();
    kv_issue(sb, 0, 0, khp, vhp, tid); CPC();
    kv_issue(sb, 1, 1, khp, vhp, tid); CPC();

    // mask2 row -> smem (x itemp), once
    float* m2s = (float*)(sm + F_M2);
    for (int i = tid; i < NN / 4; i += 256) {
        float4 f = *(const float4*)(mask2 + b * NN + i * 4);
        float4 gg = { f.x * itemp, f.y * itemp, f.z * itemp, f.w * itemp };
        *(float4*)(m2s + i * 4) = gg;
    }

    CPW(2);            // Q arrived
    __syncthreads();

    uint32_t qh[4][4];
#pragma unroll
    for (int ks = 0; ks < 4; ks++)
        ldsm4(sb + F_QH + AOFF(wm * 16 + lr, ks * 2 + lc), qh[ks]);

    const float m1r0 = mask1[b * NN + mt * 64 + wm * 16 + g] * itemp;
    const float m1r1 = mask1[b * NN + mt * 64 + wm * 16 + 8 + g] * itemp;

    float o[8][4];
#pragma unroll
    for (int j = 0; j < 8; j++)
#pragma unroll
        for (int c = 0; c < 4; c++) o[j][c] = 0.f;
    float mst0 = -1e30f, mst1 = -1e30f, l0 = 0.f, l1 = 0.f;

    float* red = (float*)(sm + F_RED);
    const int r0 = wm * 16 + g;

    for (int it = 0; it < NN / 64; it++) {
        if (it + 1 < NN / 64) { CPW(1); } else { CPW(0); }
        __syncthreads();
        const uint32_t skv = sb + F_KV + (it & 1) * FSTG;

        // ---- S = Qh*Kh ----
        float s[4][4];
#pragma unroll
        for (int j = 0; j < 4; j++)
#pragma unroll
            for (int c = 0; c < 4; c++) s[j][c] = 0.f;
#pragma unroll
        for (int ks = 0; ks < 4; ks++) {
            const int chk = ks * 2 + lc;
            uint32_t bhf[4][2];
#pragma unroll
            for (int jj = 0; jj < 2; jj++) {
                uint32_t q[4];
                ldsm4(skv + AOFF(wn * 32 + jj * 16 + lr, chk), q);
                bhf[jj * 2][0] = q[0]; bhf[jj * 2][1] = q[2];
                bhf[jj * 2 + 1][0] = q[1]; bhf[jj * 2 + 1][1] = q[3];
            }
#pragma unroll
            for (int j = 0; j < 4; j++)
                mma_hf(s[j], qh[ks], bhf[j]);
        }

        // ---- bias + WARP-LOCAL row max over this half's 32 cols ----
        float mx0 = -1e30f, mx1 = -1e30f;
#pragma unroll
        for (int j = 0; j < 4; j++) {
            float2 mm = *(float2*)(m2s + it * 64 + wn * 32 + j * 8 + t * 2);
            s[j][0] = s[j][0] + m1r0 - mm.x;
            s[j][1] = s[j][1] + m1r0 - mm.y;
            s[j][2] = s[j][2] + m1r1 - mm.x;
            s[j][3] = s[j][3] + m1r1 - mm.y;
            mx0 = fmaxf(mx0, fmaxf(s[j][0], s[j][1]));
            mx1 = fmaxf(mx1, fmaxf(s[j][2], s[j][3]));
        }
        mx0 = fmaxf(mx0, __shfl_xor_sync(0xffffffffu, mx0, 1));
        mx0 = fmaxf(mx0, __shfl_xor_sync(0xffffffffu, mx0, 2));
        mx1 = fmaxf(mx1, __shfl_xor_sync(0xffffffffu, mx1, 1));
        mx1 = fmaxf(mx1, __shfl_xor_sync(0xffffffffu, mx1, 2));

        float mn0 = fmaxf(mst0, mx0), mn1 = fmaxf(mst1, mx1);
        float c0 = __expf(mst0 - mn0), c1 = __expf(mst1 - mn1);
        mst0 = mn0; mst1 = mn1;

        float rs0 = 0.f, rs1 = 0.f;
#pragma unroll
        for (int j = 0; j < 4; j++) {
            s[j][0] = __expf(s[j][0] - mn0);
            s[j][1] = __expf(s[j][1] - mn0);
            s[j][2] = __expf(s[j][2] - mn1);
            s[j][3] = __expf(s[j][3] - mn1);
            rs0 += s[j][0] + s[j][1];
            rs1 += s[j][2] + s[j][3];
        }
        rs0 += __shfl_xor_sync(0xffffffffu, rs0, 1);
        rs0 += __shfl_xor_sync(0xffffffffu, rs0, 2);
        rs1 += __shfl_xor_sync(0xffffffffu, rs1, 1);
        rs1 += __shfl_xor_sync(0xffffffffu, rs1, 2);
        l0 = l0 * c0 + rs0;
        l1 = l1 * c1 + rs1;
#pragma unroll
        for (int j = 0; j < 8; j++) {
            o[j][0] *= c0; o[j][1] *= c0;
            o[j][2] *= c1; o[j][3] *= c1;
        }

        // ---- O += Ph*Vh (P from regs) ----
#pragma unroll
        for (int kks = 0; kks < 2; kks++) {
            const int j0 = 2 * kks, j1 = j0 + 1;
            uint32_t pah[4];
            pah[0] = pkh(s[j0][0], s[j0][1]);
            pah[1] = pkh(s[j0][2], s[j0][3]);
            pah[2] = pkh(s[j1][0], s[j1][1]);
            pah[3] = pkh(s[j1][2], s[j1][3]);

            uint32_t vhf[8][2];
#pragma unroll
            for (int jj = 0; jj < 4; jj++) {
                uint32_t q[4];
                ldsm4t(skv + 8192 + AOFF(wn * 32 + kks * 16 + lr, jj * 2 + lc), q);
                vhf[jj * 2][0] = q[0]; vhf[jj * 2][1] = q[1];
                vhf[jj * 2 + 1][0] = q[2]; vhf[jj * 2 + 1][1] = q[3];
            }
#pragma unroll
            for (int j = 0; j < 8; j++)
                mma_hf(o[j], pah, vhf[j]);
        }

        __syncthreads();
        if (it + 2 < NN / 64) {
            kv_issue(sb, it & 1, it + 2, khp, vhp, tid); CPC();
        }
    }

    // ---- epilogue: merge the two independent softmax halves, store --------
    __syncthreads();
    float* ob = (float*)(sm + F_OB);
    if (wn == 1) {
#pragma unroll
        for (int j = 0; j < 8; j++) {
            *(float2*)(ob + r0 * 68 + j * 8 + t * 2) = make_float2(o[j][0], o[j][1]);
            *(float2*)(ob + (r0 + 8) * 68 + j * 8 + t * 2) = make_float2(o[j][2], o[j][3]);
        }
        if (t == 0) {
            red[r0]      = l0;   red[r0 + 8]      = l1;
            red[64 + r0] = mst0; red[64 + r0 + 8] = mst1;
        }
    }
    __syncthreads();
    if (wn == 0) {
        float mB0 = red[64 + r0], mB1 = red[64 + r0 + 8];
        float lB0 = red[r0],      lB1 = red[r0 + 8];
        float m0f = fmaxf(mst0, mB0), m1f = fmaxf(mst1, mB1);
        float cA0 = __expf(mst0 - m0f), cB0 = __expf(mB0 - m0f);
        float cA1 = __expf(mst1 - m1f), cB1 = __expf(mB1 - m1f);
        float inv0 = 1.0f / (l0 * cA0 + lB0 * cB0);
        float inv1 = 1.0f / (l1 * cA1 + lB1 * cB1);
#pragma unroll
        for (int j = 0; j < 8; j++) {
            float2 u0 = *(float2*)(ob + r0 * 68 + j * 8 + t * 2);
            float2 u1 = *(float2*)(ob + (r0 + 8) * 68 + j * 8 + t * 2);
            float2 w0 = make_float2((o[j][0] * cA0 + u0.x * cB0) * inv0,
                                    (o[j][1] * cA0 + u0.y * cB0) * inv0);
            float2 w1 = make_float2((o[j][2] * cA1 + u1.x * cB1) * inv1,
                                    (o[j][3] * cA1 + u1.y * cB1) * inv1);
            size_t i0 = (size_t)(b * NN + mt * 64 + r0) * 384 + h * 32 + j * 4 + t;
            size_t i1 = (size_t)(b * NN + mt * 64 + r0 + 8) * 384 + h * 32 + j * 4 + t;
            g_aoh[i0] = pkh(w0.x, w0.y);
            g_aoh[i1] = pkh(w1.x, w1.y);
        }
    }
}

// ---------------------------------------------------------------------------
// LayerNorm(0.5*x1 + g_t)
// ---------------------------------------------------------------------------
__global__ __launch_bounds__(256) void ln_kernel(
    const float* __restrict__ x1, const float* __restrict__ gamma,
    const float* __restrict__ beta, float* __restrict__ out)
{
    const int row = blockIdx.x;
    const int tid = threadIdx.x;
    const float* tr = g_t + (size_t)row * NC;
    const float* xr = x1 + (size_t)row * NC;

    float z[3];
    float s = 0.f;
#pragma unroll
    for (int u = 0; u < 3; u++) {
        int idx = tid + u * 256;
        z[u] = 0.5f * xr[idx] + tr[idx];
        s += z[u];
    }

    __shared__ float red[8];
#pragma unroll
    for (int off = 16; off >= 1; off >>= 1) s += __shfl_xor_sync(0xffffffffu, s, off);
    if ((tid & 31) == 0) red[tid >> 5] = s;
    __syncthreads();
    float tot = 0.f;
#pragma unroll
    for (int w = 0; w < 8; w++) tot += red[w];
    const float mu = tot * (1.0f / NC);

    float s2 = 0.f;
#pragma unroll
    for (int u = 0; u < 3; u++) {
        float d = z[u] - mu;
        s2 += d * d;
    }
    __syncthreads();
#pragma unroll
    for (int off = 16; off >= 1; off >>= 1) s2 += __shfl_xor_sync(0xffffffffu, s2, off);
    if ((tid & 31) == 0) red[tid >> 5] = s2;
    __syncthreads();
    float tot2 = 0.f;
#pragma unroll
    for (int w = 0; w < 8; w++) tot2 += red[w];
    const float rstd = rsqrtf(tot2 * (1.0f / NC) + 1e-5f);

    float* orow = out + (size_t)row * NC;
#pragma unroll
    for (int u = 0; u < 3; u++) {
        int idx = tid + u * 256;
        orow[idx] = (z[u] - mu) * rstd * gamma[idx] + beta[idx];
    }
}

// ---------------------------------------------------------------------------
extern "C" void kernel_launch(void* const* d_in, const int* in_sizes, int n_in,
                              void* d_out, int out_size)
{
    (void)in_sizes; (void)n_in; (void)out_size;
    const float* x1    = (const float*)d_in[0];
    const float* x2    = (const float*)d_in[1];
    const float* mask1 = (const float*)d_in[2];
    const float* mask2 = (const float*)d_in[3];
    const float* Wq    = (const float*)d_in[4];
    const float* bq    = (const float*)d_in[5];
    const float* Wk    = (const float*)d_in[6];
    const float* bk    = (const float*)d_in[7];
    const float* Wv    = (const float*)d_in[8];
    const float* bv    = (const float*)d_in[9];
    const float* Wo    = (const float*)d_in[10];
    const float* bo    = (const float*)d_in[11];
    const float* temp  = (const float*)d_in[12];
    const float* gamma = (const float*)d_in[13];
    const float* beta  = (const float*)d_in[14];
    float* out = (float*)d_out;

    cudaFuncSetAttribute(mma_flash2,
                         cudaFuncAttributeMaxDynamicSharedMemorySize, ATT_SMEM);
    cudaFuncSetAttribute(mma_gemm2,
                         cudaFuncAttributeMaxDynamicSharedMemorySize, GEMM_SMEM);

    // prep: fused fp32 -> fp16 convert (single launch)
    split_all<<<(TOT4 + 255) / 256, 256>>>(x1, x2, Wq, Wk, Wv, Wo);

    // QKV projections (pure fp16)
    mma_gemm2<<<dim3(NC / 128, (NB * NN) / 128, 3), 256, GEMM_SMEM>>>(bq, bk, bv, bo, 0);
    // attention (pure fp16)
    mma_flash2<<<dim3(NN / 64, NB * NH), 256, ATT_SMEM>>>(mask1, mask2, temp);
    // output projection (pure fp16)
    mma_gemm2<<<dim3(NC / 128, (NB * NN) / 128, 1), 256, GEMM_SMEM>>>(bq, bk, bv, bo, 1);
    ln_kernel<<<NB * NN, 256>>>(x1, gamma, beta, out);
}

// round 14
// speedup vs baseline: 2.1219x; 1.0569x over previous
#include <cuda_runtime.h>
#include <cstdint>

#define NB 4
#define NN 2048
#define NC 768
#define NH 12
#define ND 64
#define WPAIR (NC * NC / 2)        // 294912 uint32 pairs per weight matrix
#define XPAIR (NB * NN * NC / 2)   // 3145728
#define QPAIR (NB * NH * NN * ND / 2)

// ---------------- scratch (device globals; no allocation allowed) ----------
__device__ uint32_t g_wh[4 * WPAIR];                     // weights: fp16 (B side)
__device__ uint32_t g_x1h[XPAIR];                        // activations: fp16 (A side)
__device__ uint32_t g_x2h[XPAIR];
__device__ uint32_t g_qh[QPAIR];                         // Q: fp16 (x0.125)
__device__ uint32_t g_kh[QPAIR];                         // K: fp16
__device__ uint32_t g_vh[QPAIR];                         // V: fp16
__device__ uint32_t g_aoh[XPAIR];                        // attention out: fp16
__device__ float    g_t[NB * NN * NC];                   // oproj out (fp32 for LN)

// ======================= helpers (sm_80-level PTX only) =====================
static __device__ __forceinline__ uint32_t smem_u32(const void* p) {
    uint32_t a;
    asm("{ .reg .u64 t; cvta.to.shared.u64 t, %1; cvt.u32.u64 %0, t; }"
        : "=r"(a) : "l"(p));
    return a;
}
// pack two fp32 -> fp16x2 (lo in low half)
static __device__ __forceinline__ uint32_t pkh(float lo, float hi) {
    uint32_t r;
    asm("cvt.rn.f16x2.f32 %0, %1, %2;" : "=r"(r) : "f"(hi), "f"(lo));
    return r;
}
// packed 2^x on fp16 pairs
static __device__ __forceinline__ uint32_t ex2h2(uint32_t x) {
    uint32_t r;
    asm("ex2.approx.f16x2 %0, %1;" : "=r"(r) : "r"(x));
    return r;
}
static __device__ __forceinline__ void ldsm4(uint32_t a, uint32_t* r) {
    asm volatile("ldmatrix.sync.aligned.m8n8.x4.shared.b16 {%0,%1,%2,%3}, [%4];"
                 : "=r"(r[0]), "=r"(r[1]), "=r"(r[2]), "=r"(r[3]) : "r"(a));
}
static __device__ __forceinline__ void ldsm4t(uint32_t a, uint32_t* r) {
    asm volatile("ldmatrix.sync.aligned.m8n8.x4.trans.shared.b16 {%0,%1,%2,%3}, [%4];"
                 : "=r"(r[0]), "=r"(r[1]), "=r"(r[2]), "=r"(r[3]) : "r"(a));
}
static __device__ __forceinline__ void mma_hf(float* c, const uint32_t* a, const uint32_t* b) {
    asm volatile("mma.sync.aligned.m16n8k16.row.col.f32.f16.f16.f32 "
                 "{%0,%1,%2,%3},{%4,%5,%6,%7},{%8,%9},{%0,%1,%2,%3};"
                 : "+f"(c[0]), "+f"(c[1]), "+f"(c[2]), "+f"(c[3])
                 : "r"(a[0]), "r"(a[1]), "r"(a[2]), "r"(a[3]),
                   "r"(b[0]), "r"(b[1]));
}
#define CPA(dst, src) \
    asm volatile("cp.async.cg.shared.global [%0], [%1], 16;" :: "r"(dst), "l"(src))
#define CPC() asm volatile("cp.async.commit_group;" ::: "memory")
#define CPW(n) asm volatile("cp.async.wait_group %0;" :: "n"(n) : "memory")

// swizzled smem byte offsets (16B granules, conflict-free ldmatrix)
#define GOFF(r, ch) ((((r) >> 1) * 128) + ((((((r) & 1) << 2) | (ch)) ^ (((r) >> 1) & 7)) * 16))
#define AOFF(r, ch) (((r) * 128) + ((((ch) ^ ((r) & 7))) * 16))

// ======================= prep: fused fp32 -> fp16 convert ===================
#define XN4 (NB * NN * NC / 4)
#define WN4 (NC * NC / 4)
#define TOT4 (2 * XN4 + 4 * WN4)

__global__ __launch_bounds__(256) void split_all(
    const float* __restrict__ x1, const float* __restrict__ x2,
    const float* __restrict__ Wq, const float* __restrict__ Wk,
    const float* __restrict__ Wv, const float* __restrict__ Wo)
{
    int i = blockIdx.x * blockDim.x + threadIdx.x;
    if (i >= TOT4) return;
    const float* src; uint32_t* dh; int li;
    if (i < XN4)          { src = x1; dh = g_x1h; li = i; }
    else if (i < 2 * XN4) { src = x2; dh = g_x2h; li = i - XN4; }
    else {
        int j = i - 2 * XN4;
        int w = j / WN4;
        li = j - w * WN4;
        src = (w == 0) ? Wq : (w == 1) ? Wk : (w == 2) ? Wv : Wo;
        dh = g_wh + (size_t)w * WPAIR;
    }
    float4 f = ((const float4*)src)[li];
    ((uint2*)dh)[li] = make_uint2(pkh(f.x, f.y), pkh(f.z, f.w));
}

// ======================= pure-fp16 mma GEMM (R12-proven) =====================
#define GSTG 16384
#define GEMM_SMEM (2 * GSTG)      // 32768

static __device__ __forceinline__ void gemm_issue(
    uint32_t sb, int buf, int c, const uint32_t* Ah,
    const uint32_t* Wh, int m0, int n0, int tid)
{
#pragma unroll
    for (int p = 0; p < 2; p++) {
        int cid = tid + p * 256;
        int r = cid >> 2, ch = cid & 3;
        size_t sa = (size_t)(m0 + r) * 384 + c * 16 + ch * 4;
        size_t sw = (size_t)(n0 + r) * 384 + c * 16 + ch * 4;
        uint32_t d = sb + buf * GSTG + GOFF(r, ch);
        CPA(d,        Ah + sa);
        CPA(d + 8192, Wh + sw);
    }
}

__global__ __launch_bounds__(256) void mma_gemm2(
    const float* __restrict__ bq, const float* __restrict__ bk,
    const float* __restrict__ bv, const float* __restrict__ bo, int phase)
{
    extern __shared__ __align__(128) char gsm[];
    const uint32_t sb = smem_u32(gsm);
    const int mode = phase ? 3 : (int)blockIdx.z;
    const uint32_t* Ah = (mode == 0) ? g_x1h : (mode == 3) ? g_aoh : g_x2h;
    const uint32_t* Wh = g_wh + (size_t)mode * WPAIR;
    const float* bias = (mode == 0) ? bq : (mode == 1) ? bk : (mode == 2) ? bv : bo;

    const int n0 = blockIdx.x * 128;
    const int m0 = blockIdx.y * 128;
    const int tid  = threadIdx.x;
    const int lane = tid & 31;
    const int wid  = tid >> 5;
    const int wm = wid & 3;
    const int wn = wid >> 2;
    const int g  = lane >> 2;
    const int t  = lane & 3;
    const int lr = lane & 15;
    const int lc = lane >> 4;

    float acc[2][8][4];
#pragma unroll
    for (int i = 0; i < 2; i++)
#pragma unroll
        for (int j = 0; j < 8; j++)
#pragma unroll
            for (int c = 0; c < 4; c++) acc[i][j][c] = 0.f;

    gemm_issue(sb, 0, 0, Ah, Wh, m0, n0, tid); CPC();
    gemm_issue(sb, 1, 1, Ah, Wh, m0, n0, tid); CPC();

    for (int c = 0; c < NC / 32; c++) {
        if (c + 1 < NC / 32) { CPW(1); } else { CPW(0); }
        __syncthreads();
        const uint32_t s2 = sb + (c & 1) * GSTG;

#pragma unroll
        for (int ks = 0; ks < 2; ks++) {
            const int chk = ks * 2 + lc;
            uint32_t ah[2][4], bh[8][2];
#pragma unroll
            for (int mf = 0; mf < 2; mf++)
                ldsm4(s2 + GOFF(wm * 32 + mf * 16 + lr, chk), ah[mf]);
#pragma unroll
            for (int jj = 0; jj < 4; jj++) {
                uint32_t q[4];
                ldsm4(s2 + 8192 + GOFF(wn * 64 + jj * 16 + lr, chk), q);
                bh[jj * 2][0] = q[0]; bh[jj * 2][1] = q[2];
                bh[jj * 2 + 1][0] = q[1]; bh[jj * 2 + 1][1] = q[3];
            }
#pragma unroll
            for (int mf = 0; mf < 2; mf++)
#pragma unroll
                for (int j = 0; j < 8; j++)
                    mma_hf(acc[mf][j], ah[mf], bh[j]);
        }
        __syncthreads();
        if (c + 2 < NC / 32) {
            gemm_issue(sb, c & 1, c + 2, Ah, Wh, m0, n0, tid); CPC();
        }
    }

#pragma unroll
    for (int mf = 0; mf < 2; mf++) {
        int r = m0 + wm * 32 + mf * 16 + g;
#pragma unroll
        for (int j = 0; j < 8; j++) {
            int cg = n0 + wn * 64 + j * 8 + t * 2;
            float bx = bias[cg], by = bias[cg + 1];
            float2 v0 = { acc[mf][j][0] + bx, acc[mf][j][1] + by };
            float2 v1 = { acc[mf][j][2] + bx, acc[mf][j][3] + by };
            if (mode == 3) {
                *(float2*)(g_t + (size_t)r * NC + cg) = v0;
                *(float2*)(g_t + (size_t)(r + 8) * NC + cg) = v1;
            } else {
                int b = r >> 11, h = cg >> 6, dp = (cg & 63) >> 1;
                size_t base = ((size_t)(b * NH + h)) * NN;
                size_t i0 = (base + (r & (NN - 1))) * 32 + dp;
                size_t i1 = (base + ((r + 8) & (NN - 1))) * 32 + dp;
                if (mode == 0) {
                    v0.x *= 0.125f; v0.y *= 0.125f;
                    v1.x *= 0.125f; v1.y *= 0.125f;
                    g_qh[i0] = pkh(v0.x, v0.y);
                    g_qh[i1] = pkh(v1.x, v1.y);
                } else {
                    uint32_t* dst = (mode == 1) ? g_kh : g_vh;
                    dst[i0] = pkh(v0.x, v0.y);
                    dst[i1] = pkh(v1.x, v1.y);
                }
            }
        }
    }
}

// ======================= pure-fp16 mma flash attention =======================
// CTA 64 Q-rows; 8 warps 4(M)x2(N). Independent per-half online softmax,
// merged once in epilogue. P via ex2.approx.f16x2 (packed); row sums via
// ones-MMA (exact fp32 sum of the SAME fp16 P used in PV).
#define F_M2  0
#define F_RED 8192
#define F_QH  8704
#define F_KV  16896
#define F_OB  16896                       // aliases KV (used only after loop)
#define FSTG  16384
#define ATT_SMEM (F_KV + 2 * FSTG)        // 49664

static __device__ __forceinline__ void kv_issue(
    uint32_t sb, int buf, int it, const uint32_t* kh, const uint32_t* vh, int tid)
{
#pragma unroll
    for (int p = 0; p < 2; p++) {
        int cid = tid + p * 256;
        int r = cid >> 3, ch = cid & 7;
        size_t src = (size_t)(it * 64 + r) * 32 + ch * 4;
        uint32_t d = sb + F_KV + buf * FSTG + AOFF(r, ch);
        CPA(d,         kh + src);
        CPA(d + 8192,  vh + src);
    }
}

__global__ __launch_bounds__(256) void mma_flash2(
    const float* __restrict__ mask1, const float* __restrict__ mask2,
    const float* __restrict__ temp_p)
{
    extern __shared__ __align__(128) char sm[];
    const uint32_t sb = smem_u32(sm);
    const int mt = blockIdx.x;
    const int bh = blockIdx.y;
    const int b  = bh / NH;
    const int h  = bh % NH;
    const int tid  = threadIdx.x;
    const int lane = tid & 31;
    const int wid  = tid >> 5;
    const int wm = wid & 3;
    const int wn = wid >> 2;
    const int g  = lane >> 2;
    const int t  = lane & 3;
    const int lr = lane & 15;
    const int lc = lane >> 4;

    const float itemp = 1.0f / temp_p[0];
    const float L2E = 1.4426950408889634f;

    const uint32_t* qhp = g_qh + ((size_t)bh * NN + mt * 64) * 32;
    const uint32_t* khp = g_kh + (size_t)bh * NN * 32;
    const uint32_t* vhp = g_vh + (size_t)bh * NN * 32;

    // Q tile (group 0)
    {
        int cid = tid;
        int r = cid >> 2, ch = (cid & 3) << 1;
        size_t src = (size_t)r * 32 + ch * 4;
        CPA(sb + F_QH + AOFF(r, ch),     qhp + src);
        CPA(sb + F_QH + AOFF(r, ch + 1), qhp + src + 4);
    }
    CPC();
    kv_issue(sb, 0, 0, khp, vhp, tid); CPC();
    kv_issue(sb, 1, 1, khp, vhp, tid); CPC();

    // mask2 row -> smem (x itemp), once
    float* m2s = (float*)(sm + F_M2);
    for (int i = tid; i < NN / 4; i += 256) {
        float4 f = *(const float4*)(mask2 + b * NN + i * 4);
        float4 gg = { f.x * itemp, f.y * itemp, f.z * itemp, f.w * itemp };
        *(float4*)(m2s + i * 4) = gg;
    }

    CPW(2);            // Q arrived
    __syncthreads();

    uint32_t qh[4][4];
#pragma unroll
    for (int ks = 0; ks < 4; ks++)
        ldsm4(sb + F_QH + AOFF(wm * 16 + lr, ks * 2 + lc), qh[ks]);

    const float m1r0 = mask1[b * NN + mt * 64 + wm * 16 + g] * itemp;
    const float m1r1 = mask1[b * NN + mt * 64 + wm * 16 + 8 + g] * itemp;

    float o[8][4];
#pragma unroll
    for (int j = 0; j < 8; j++)
#pragma unroll
        for (int c = 0; c < 4; c++) o[j][c] = 0.f;
    float mst0 = -1e30f, mst1 = -1e30f, l0 = 0.f, l1 = 0.f;

    float* red = (float*)(sm + F_RED);
    const int r0 = wm * 16 + g;
    const uint32_t ONES2[2] = { 0x3C003C00u, 0x3C003C00u };

    for (int it = 0; it < NN / 64; it++) {
        if (it + 1 < NN / 64) { CPW(1); } else { CPW(0); }
        __syncthreads();
        const uint32_t skv = sb + F_KV + (it & 1) * FSTG;

        // ---- S = Qh*Kh ----
        float s[4][4];
#pragma unroll
        for (int j = 0; j < 4; j++)
#pragma unroll
            for (int c = 0; c < 4; c++) s[j][c] = 0.f;
#pragma unroll
        for (int ks = 0; ks < 4; ks++) {
            const int chk = ks * 2 + lc;
            uint32_t bhf[4][2];
#pragma unroll
            for (int jj = 0; jj < 2; jj++) {
                uint32_t q[4];
                ldsm4(skv + AOFF(wn * 32 + jj * 16 + lr, chk), q);
                bhf[jj * 2][0] = q[0]; bhf[jj * 2][1] = q[2];
                bhf[jj * 2 + 1][0] = q[1]; bhf[jj * 2 + 1][1] = q[3];
            }
#pragma unroll
            for (int j = 0; j < 4; j++)
                mma_hf(s[j], qh[ks], bhf[j]);
        }

        // ---- bias + WARP-LOCAL row max (in log2-domain scale) ----
        float mx0 = -1e30f, mx1 = -1e30f;
#pragma unroll
        for (int j = 0; j < 4; j++) {
            float2 mm = *(float2*)(m2s + it * 64 + wn * 32 + j * 8 + t * 2);
            s[j][0] = s[j][0] + m1r0 - mm.x;
            s[j][1] = s[j][1] + m1r0 - mm.y;
            s[j][2] = s[j][2] + m1r1 - mm.x;
            s[j][3] = s[j][3] + m1r1 - mm.y;
            mx0 = fmaxf(mx0, fmaxf(s[j][0], s[j][1]));
            mx1 = fmaxf(mx1, fmaxf(s[j][2], s[j][3]));
        }
        mx0 = fmaxf(mx0, __shfl_xor_sync(0xffffffffu, mx0, 1));
        mx0 = fmaxf(mx0, __shfl_xor_sync(0xffffffffu, mx0, 2));
        mx1 = fmaxf(mx1, __shfl_xor_sync(0xffffffffu, mx1, 1));
        mx1 = fmaxf(mx1, __shfl_xor_sync(0xffffffffu, mx1, 2));

        float mn0 = fmaxf(mst0, mx0), mn1 = fmaxf(mst1, mx1);
        float c0 = __expf(mst0 - mn0), c1 = __expf(mst1 - mn1);
        mst0 = mn0; mst1 = mn1;

#pragma unroll
        for (int j = 0; j < 8; j++) {
            o[j][0] *= c0; o[j][1] *= c0;
            o[j][2] *= c1; o[j][3] *= c1;
        }

        // ---- P = ex2((s-m)*L2E) packed fp16; O += P*Vh; l-sums via ones-MMA
        float cl[4] = { 0.f, 0.f, 0.f, 0.f };
#pragma unroll
        for (int kks = 0; kks < 2; kks++) {
            const int j0 = 2 * kks, j1 = j0 + 1;
            uint32_t pah[4];
            pah[0] = ex2h2(pkh((s[j0][0] - mn0) * L2E, (s[j0][1] - mn0) * L2E));
            pah[1] = ex2h2(pkh((s[j0][2] - mn1) * L2E, (s[j0][3] - mn1) * L2E));
            pah[2] = ex2h2(pkh((s[j1][0] - mn0) * L2E, (s[j1][1] - mn0) * L2E));
            pah[3] = ex2h2(pkh((s[j1][2] - mn1) * L2E, (s[j1][3] - mn1) * L2E));

            mma_hf(cl, pah, ONES2);      // exact fp32 row-sums of fp16 P

            uint32_t vhf[8][2];
#pragma unroll
            for (int jj = 0; jj < 4; jj++) {
                uint32_t q[4];
                ldsm4t(skv + 8192 + AOFF(wn * 32 + kks * 16 + lr, jj * 2 + lc), q);
                vhf[jj * 2][0] = q[0]; vhf[jj * 2][1] = q[1];
                vhf[jj * 2 + 1][0] = q[2]; vhf[jj * 2 + 1][1] = q[3];
            }
#pragma unroll
            for (int j = 0; j < 8; j++)
                mma_hf(o[j], pah, vhf[j]);
        }
        l0 = l0 * c0 + cl[0];
        l1 = l1 * c1 + cl[2];

        __syncthreads();
        if (it + 2 < NN / 64) {
            kv_issue(sb, it & 1, it + 2, khp, vhp, tid); CPC();
        }
    }

    // ---- epilogue: merge the two independent softmax halves, store --------
    __syncthreads();
    float* ob = (float*)(sm + F_OB);
    if (wn == 1) {
#pragma unroll
        for (int j = 0; j < 8; j++) {
            *(float2*)(ob + r0 * 68 + j * 8 + t * 2) = make_float2(o[j][0], o[j][1]);
            *(float2*)(ob + (r0 + 8) * 68 + j * 8 + t * 2) = make_float2(o[j][2], o[j][3]);
        }
        if (t == 0) {
            red[r0]      = l0;   red[r0 + 8]      = l1;
            red[64 + r0] = mst0; red[64 + r0 + 8] = mst1;
        }
    }
    __syncthreads();
    if (wn == 0) {
        float mB0 = red[64 + r0], mB1 = red[64 + r0 + 8];
        float lB0 = red[r0],      lB1 = red[r0 + 8];
        float m0f = fmaxf(mst0, mB0), m1f = fmaxf(mst1, mB1);
        float cA0 = __expf(mst0 - m0f), cB0 = __expf(mB0 - m0f);
        float cA1 = __expf(mst1 - m1f), cB1 = __expf(mB1 - m1f);
        float inv0 = 1.0f / (l0 * cA0 + lB0 * cB0);
        float inv1 = 1.0f / (l1 * cA1 + lB1 * cB1);
#pragma unroll
        for (int j = 0; j < 8; j++) {
            float2 u0 = *(float2*)(ob + r0 * 68 + j * 8 + t * 2);
            float2 u1 = *(float2*)(ob + (r0 + 8) * 68 + j * 8 + t * 2);
            float2 w0 = make_float2((o[j][0] * cA0 + u0.x * cB0) * inv0,
                                    (o[j][1] * cA0 + u0.y * cB0) * inv0);
            float2 w1 = make_float2((o[j][2] * cA1 + u1.x * cB1) * inv1,
                                    (o[j][3] * cA1 + u1.y * cB1) * inv1);
            size_t i0 = (size_t)(b * NN + mt * 64 + r0) * 384 + h * 32 + j * 4 + t;
            size_t i1 = (size_t)(b * NN + mt * 64 + r0 + 8) * 384 + h * 32 + j * 4 + t;
            g_aoh[i0] = pkh(w0.x, w0.y);
            g_aoh[i1] = pkh(w1.x, w1.y);
        }
    }
}

// ---------------------------------------------------------------------------
// LayerNorm(0.5*x1 + g_t)
// ---------------------------------------------------------------------------
__global__ __launch_bounds__(256) void ln_kernel(
    const float* __restrict__ x1, const float* __restrict__ gamma,
    const float* __restrict__ beta, float* __restrict__ out)
{
    const int row = blockIdx.x;
    const int tid = threadIdx.x;
    const float* tr = g_t + (size_t)row * NC;
    const float* xr = x1 + (size_t)row * NC;

    float z[3];
    float s = 0.f;
#pragma unroll
    for (int u = 0; u < 3; u++) {
        int idx = tid + u * 256;
        z[u] = 0.5f * xr[idx] + tr[idx];
        s += z[u];
    }

    __shared__ float red[8];
#pragma unroll
    for (int off = 16; off >= 1; off >>= 1) s += __shfl_xor_sync(0xffffffffu, s, off);
    if ((tid & 31) == 0) red[tid >> 5] = s;
    __syncthreads();
    float tot = 0.f;
#pragma unroll
    for (int w = 0; w < 8; w++) tot += red[w];
    const float mu = tot * (1.0f / NC);

    float s2 = 0.f;
#pragma unroll
    for (int u = 0; u < 3; u++) {
        float d = z[u] - mu;
        s2 += d * d;
    }
    __syncthreads();
#pragma unroll
    for (int off = 16; off >= 1; off >>= 1) s2 += __shfl_xor_sync(0xffffffffu, s2, off);
    if ((tid & 31) == 0) red[tid >> 5] = s2;
    __syncthreads();
    float tot2 = 0.f;
#pragma unroll
    for (int w = 0; w < 8; w++) tot2 += red[w];
    const float rstd = rsqrtf(tot2 * (1.0f / NC) + 1e-5f);

    float* orow = out + (size_t)row * NC;
#pragma unroll
    for (int u = 0; u < 3; u++) {
        int idx = tid + u * 256;
        orow[idx] = (z[u] - mu) * rstd * gamma[idx] + beta[idx];
    }
}

// ---------------------------------------------------------------------------
extern "C" void kernel_launch(void* const* d_in, const int* in_sizes, int n_in,
                              void* d_out, int out_size)
{
    (void)in_sizes; (void)n_in; (void)out_size;
    const float* x1    = (const float*)d_in[0];
    const float* x2    = (const float*)d_in[1];
    const float* mask1 = (const float*)d_in[2];
    const float* mask2 = (const float*)d_in[3];
    const float* Wq    = (const float*)d_in[4];
    const float* bq    = (const float*)d_in[5];
    const float* Wk    = (const float*)d_in[6];
    const float* bk    = (const float*)d_in[7];
    const float* Wv    = (const float*)d_in[8];
    const float* bv    = (const float*)d_in[9];
    const float* Wo    = (const float*)d_in[10];
    const float* bo    = (const float*)d_in[11];
    const float* temp  = (const float*)d_in[12];
    const float* gamma = (const float*)d_in[13];
    const float* beta  = (const float*)d_in[14];
    float* out = (float*)d_out;

    cudaFuncSetAttribute(mma_flash2,
                         cudaFuncAttributeMaxDynamicSharedMemorySize, ATT_SMEM);
    cudaFuncSetAttribute(mma_gemm2,
                         cudaFuncAttributeMaxDynamicSharedMemorySize, GEMM_SMEM);

    // prep: fused fp32 -> fp16 convert (single launch)
    split_all<<<(TOT4 + 255) / 256, 256>>>(x1, x2, Wq, Wk, Wv, Wo);

    // QKV projections (pure fp16)
    mma_gemm2<<<dim3(NC / 128, (NB * NN) / 128, 3), 256, GEMM_SMEM>>>(bq, bk, bv, bo, 0);
    // attention (pure fp16, ex2.f16x2 softmax, ones-MMA row sums)
    mma_flash2<<<dim3(NN / 64, NB * NH), 256, ATT_SMEM>>>(mask1, mask2, temp);
    // output projection (pure fp16)
    mma_gemm2<<<dim3(NC / 128, (NB * NN) / 128, 1), 256, GEMM_SMEM>>>(bq, bk, bv, bo, 1);
    ln_kernel<<<NB * NN, 256>>>(x1, gamma, beta, out);
}

// round 15
// speedup vs baseline: 2.2363x; 1.0539x over previous
#include <cuda_runtime.h>
#include <cstdint>

#define NB 4
#define NN 2048
#define NC 768
#define NH 12
#define ND 64
#define WPAIR (NC * NC / 2)        // 294912 uint32 pairs per weight matrix
#define XPAIR (NB * NN * NC / 2)   // 3145728
#define QPAIR (NB * NH * NN * ND / 2)

// ---------------- scratch (device globals; no allocation allowed) ----------
__device__ uint32_t g_wh[4 * WPAIR];                     // weights: fp16 (B side)
__device__ uint32_t g_x1h[XPAIR];                        // activations: fp16 (A side)
__device__ uint32_t g_x2h[XPAIR];
__device__ uint32_t g_qh[QPAIR];                         // Q: fp16 (x0.125)
__device__ uint32_t g_kh[QPAIR];                         // K: fp16
__device__ uint32_t g_vh[QPAIR];                         // V: fp16
__device__ uint32_t g_aoh[XPAIR];                        // attention out: fp16
__device__ float    g_t[NB * NN * NC];                   // oproj out (fp32 for LN)

// ======================= helpers (sm_80-level PTX only) =====================
static __device__ __forceinline__ uint32_t smem_u32(const void* p) {
    uint32_t a;
    asm("{ .reg .u64 t; cvta.to.shared.u64 t, %1; cvt.u32.u64 %0, t; }"
        : "=r"(a) : "l"(p));
    return a;
}
static __device__ __forceinline__ uint32_t pkh(float lo, float hi) {
    uint32_t r;
    asm("cvt.rn.f16x2.f32 %0, %1, %2;" : "=r"(r) : "f"(hi), "f"(lo));
    return r;
}
static __device__ __forceinline__ uint32_t ex2h2(uint32_t x) {
    uint32_t r;
    asm("ex2.approx.f16x2 %0, %1;" : "=r"(r) : "r"(x));
    return r;
}
static __device__ __forceinline__ void ldsm4(uint32_t a, uint32_t* r) {
    asm volatile("ldmatrix.sync.aligned.m8n8.x4.shared.b16 {%0,%1,%2,%3}, [%4];"
                 : "=r"(r[0]), "=r"(r[1]), "=r"(r[2]), "=r"(r[3]) : "r"(a));
}
static __device__ __forceinline__ void ldsm4t(uint32_t a, uint32_t* r) {
    asm volatile("ldmatrix.sync.aligned.m8n8.x4.trans.shared.b16 {%0,%1,%2,%3}, [%4];"
                 : "=r"(r[0]), "=r"(r[1]), "=r"(r[2]), "=r"(r[3]) : "r"(a));
}
static __device__ __forceinline__ void mma_hf(float* c, const uint32_t* a, const uint32_t* b) {
    asm volatile("mma.sync.aligned.m16n8k16.row.col.f32.f16.f16.f32 "
                 "{%0,%1,%2,%3},{%4,%5,%6,%7},{%8,%9},{%0,%1,%2,%3};"
                 : "+f"(c[0]), "+f"(c[1]), "+f"(c[2]), "+f"(c[3])
                 : "r"(a[0]), "r"(a[1]), "r"(a[2]), "r"(a[3]),
                   "r"(b[0]), "r"(b[1]));
}
#define CPA(dst, src) \
    asm volatile("cp.async.cg.shared.global [%0], [%1], 16;" :: "r"(dst), "l"(src))
#define CPC() asm volatile("cp.async.commit_group;" ::: "memory")
#define CPW(n) asm volatile("cp.async.wait_group %0;" :: "n"(n) : "memory")

// 128B-row swizzled smem byte offset (rows of 64 fp16)
#define AOFF(r, ch) (((r) * 128) + ((((ch) ^ ((r) & 7))) * 16))

// ======================= prep: fused fp32 -> fp16 convert ===================
#define XN4 (NB * NN * NC / 4)
#define WN4 (NC * NC / 4)
#define TOT4 (2 * XN4 + 4 * WN4)

__global__ __launch_bounds__(256) void split_all(
    const float* __restrict__ x1, const float* __restrict__ x2,
    const float* __restrict__ Wq, const float* __restrict__ Wk,
    const float* __restrict__ Wv, const float* __restrict__ Wo)
{
    int i = blockIdx.x * blockDim.x + threadIdx.x;
    if (i >= TOT4) return;
    const float* src; uint32_t* dh; int li;
    if (i < XN4)          { src = x1; dh = g_x1h; li = i; }
    else if (i < 2 * XN4) { src = x2; dh = g_x2h; li = i - XN4; }
    else {
        int j = i - 2 * XN4;
        int w = j / WN4;
        li = j - w * WN4;
        src = (w == 0) ? Wq : (w == 1) ? Wk : (w == 2) ? Wv : Wo;
        dh = g_wh + (size_t)w * WPAIR;
    }
    float4 f = ((const float4*)src)[li];
    ((uint2*)dh)[li] = make_uint2(pkh(f.x, f.y), pkh(f.z, f.w));
}

// ======================= pure-fp16 mma GEMM (BK=64) ==========================
// C[M,768] = A @ W^T + bias; D = Ah*Wh. CTA 128x128, BK=64, 8 warps (4M x 2N).
// 2-stage cp.async; stage: A 16K | B 16K = 32KB; 2 stages = 64KB.
#define GSTG 32768
#define GEMM_SMEM (2 * GSTG)      // 65536

static __device__ __forceinline__ void gemm_issue(
    uint32_t sb, int buf, int c, const uint32_t* Ah,
    const uint32_t* Wh, int m0, int n0, int tid)
{
#pragma unroll
    for (int p = 0; p < 4; p++) {
        int cid = tid + p * 256;
        int r = cid >> 3, ch = cid & 7;
        size_t sa = (size_t)(m0 + r) * 384 + c * 32 + ch * 4;
        size_t sw = (size_t)(n0 + r) * 384 + c * 32 + ch * 4;
        uint32_t d = sb + buf * GSTG + AOFF(r, ch);
        CPA(d,         Ah + sa);
        CPA(d + 16384, Wh + sw);
    }
}

__global__ __launch_bounds__(256) void mma_gemm2(
    const float* __restrict__ bq, const float* __restrict__ bk,
    const float* __restrict__ bv, const float* __restrict__ bo, int phase)
{
    extern __shared__ __align__(128) char gsm[];
    const uint32_t sb = smem_u32(gsm);
    const int mode = phase ? 3 : (int)blockIdx.z;
    const uint32_t* Ah = (mode == 0) ? g_x1h : (mode == 3) ? g_aoh : g_x2h;
    const uint32_t* Wh = g_wh + (size_t)mode * WPAIR;
    const float* bias = (mode == 0) ? bq : (mode == 1) ? bk : (mode == 2) ? bv : bo;

    const int n0 = blockIdx.x * 128;
    const int m0 = blockIdx.y * 128;
    const int tid  = threadIdx.x;
    const int lane = tid & 31;
    const int wid  = tid >> 5;
    const int wm = wid & 3;
    const int wn = wid >> 2;
    const int g  = lane >> 2;
    const int t  = lane & 3;
    const int lr = lane & 15;
    const int lc = lane >> 4;

    float acc[2][8][4];
#pragma unroll
    for (int i = 0; i < 2; i++)
#pragma unroll
        for (int j = 0; j < 8; j++)
#pragma unroll
            for (int c = 0; c < 4; c++) acc[i][j][c] = 0.f;

    gemm_issue(sb, 0, 0, Ah, Wh, m0, n0, tid); CPC();
    gemm_issue(sb, 1, 1, Ah, Wh, m0, n0, tid); CPC();

    for (int c = 0; c < NC / 64; c++) {
        if (c + 1 < NC / 64) { CPW(1); } else { CPW(0); }
        __syncthreads();
        const uint32_t s2 = sb + (c & 1) * GSTG;

#pragma unroll
        for (int ks = 0; ks < 4; ks++) {
            const int chk = ks * 2 + lc;
            uint32_t ah[2][4], bh[8][2];
#pragma unroll
            for (int mf = 0; mf < 2; mf++)
                ldsm4(s2 + AOFF(wm * 32 + mf * 16 + lr, chk), ah[mf]);
#pragma unroll
            for (int jj = 0; jj < 4; jj++) {
                uint32_t q[4];
                ldsm4(s2 + 16384 + AOFF(wn * 64 + jj * 16 + lr, chk), q);
                bh[jj * 2][0] = q[0]; bh[jj * 2][1] = q[2];
                bh[jj * 2 + 1][0] = q[1]; bh[jj * 2 + 1][1] = q[3];
            }
#pragma unroll
            for (int mf = 0; mf < 2; mf++)
#pragma unroll
                for (int j = 0; j < 8; j++)
                    mma_hf(acc[mf][j], ah[mf], bh[j]);
        }
        __syncthreads();
        if (c + 2 < NC / 64) {
            gemm_issue(sb, c & 1, c + 2, Ah, Wh, m0, n0, tid); CPC();
        }
    }

#pragma unroll
    for (int mf = 0; mf < 2; mf++) {
        int r = m0 + wm * 32 + mf * 16 + g;
#pragma unroll
        for (int j = 0; j < 8; j++) {
            int cg = n0 + wn * 64 + j * 8 + t * 2;
            float bx = bias[cg], by = bias[cg + 1];
            float2 v0 = { acc[mf][j][0] + bx, acc[mf][j][1] + by };
            float2 v1 = { acc[mf][j][2] + bx, acc[mf][j][3] + by };
            if (mode == 3) {
                *(float2*)(g_t + (size_t)r * NC + cg) = v0;
                *(float2*)(g_t + (size_t)(r + 8) * NC + cg) = v1;
            } else {
                int b = r >> 11, h = cg >> 6, dp = (cg & 63) >> 1;
                size_t base = ((size_t)(b * NH + h)) * NN;
                size_t i0 = (base + (r & (NN - 1))) * 32 + dp;
                size_t i1 = (base + ((r + 8) & (NN - 1))) * 32 + dp;
                if (mode == 0) {
                    v0.x *= 0.125f; v0.y *= 0.125f;
                    v1.x *= 0.125f; v1.y *= 0.125f;
                    g_qh[i0] = pkh(v0.x, v0.y);
                    g_qh[i1] = pkh(v1.x, v1.y);
                } else {
                    uint32_t* dst = (mode == 1) ? g_kh : g_vh;
                    dst[i0] = pkh(v0.x, v0.y);
                    dst[i1] = pkh(v1.x, v1.y);
                }
            }
        }
    }
}

// ======================= pure-fp16 mma flash attention (R13) =================
#define F_M2  0
#define F_RED 8192
#define F_QH  8704
#define F_KV  16896
#define F_OB  16896                       // aliases KV (used only after loop)
#define FSTG  16384
#define ATT_SMEM (F_KV + 2 * FSTG)        // 49664

static __device__ __forceinline__ void kv_issue(
    uint32_t sb, int buf, int it, const uint32_t* kh, const uint32_t* vh, int tid)
{
#pragma unroll
    for (int p = 0; p < 2; p++) {
        int cid = tid + p * 256;
        int r = cid >> 3, ch = cid & 7;
        size_t src = (size_t)(it * 64 + r) * 32 + ch * 4;
        uint32_t d = sb + F_KV + buf * FSTG + AOFF(r, ch);
        CPA(d,         kh + src);
        CPA(d + 8192,  vh + src);
    }
}

__global__ __launch_bounds__(256) void mma_flash2(
    const float* __restrict__ mask1, const float* __restrict__ mask2,
    const float* __restrict__ temp_p)
{
    extern __shared__ __align__(128) char sm[];
    const uint32_t sb = smem_u32(sm);
    const int mt = blockIdx.x;
    const int bh = blockIdx.y;
    const int b  = bh / NH;
    const int h  = bh % NH;
    const int tid  = threadIdx.x;
    const int lane = tid & 31;
    const int wid  = tid >> 5;
    const int wm = wid & 3;
    const int wn = wid >> 2;
    const int g  = lane >> 2;
    const int t  = lane & 3;
    const int lr = lane & 15;
    const int lc = lane >> 4;

    const float itemp = 1.0f / temp_p[0];
    const float L2E = 1.4426950408889634f;

    const uint32_t* qhp = g_qh + ((size_t)bh * NN + mt * 64) * 32;
    const uint32_t* khp = g_kh + (size_t)bh * NN * 32;
    const uint32_t* vhp = g_vh + (size_t)bh * NN * 32;

    // Q tile (group 0)
    {
        int cid = tid;
        int r = cid >> 2, ch = (cid & 3) << 1;
        size_t src = (size_t)r * 32 + ch * 4;
        CPA(sb + F_QH + AOFF(r, ch),     qhp + src);
        CPA(sb + F_QH + AOFF(r, ch + 1), qhp + src + 4);
    }
    CPC();
    kv_issue(sb, 0, 0, khp, vhp, tid); CPC();
    kv_issue(sb, 1, 1, khp, vhp, tid); CPC();

    // mask2 row -> smem (x itemp), once
    float* m2s = (float*)(sm + F_M2);
    for (int i = tid; i < NN / 4; i += 256) {
        float4 f = *(const float4*)(mask2 + b * NN + i * 4);
        float4 gg = { f.x * itemp, f.y * itemp, f.z * itemp, f.w * itemp };
        *(float4*)(m2s + i * 4) = gg;
    }

    CPW(2);            // Q arrived
    __syncthreads();

    uint32_t qh[4][4];
#pragma unroll
    for (int ks = 0; ks < 4; ks++)
        ldsm4(sb + F_QH + AOFF(wm * 16 + lr, ks * 2 + lc), qh[ks]);

    const float m1r0 = mask1[b * NN + mt * 64 + wm * 16 + g] * itemp;
    const float m1r1 = mask1[b * NN + mt * 64 + wm * 16 + 8 + g] * itemp;

    float o[8][4];
#pragma unroll
    for (int j = 0; j < 8; j++)
#pragma unroll
        for (int c = 0; c < 4; c++) o[j][c] = 0.f;
    float mst0 = -1e30f, mst1 = -1e30f, l0 = 0.f, l1 = 0.f;

    float* red = (float*)(sm + F_RED);
    const int r0 = wm * 16 + g;
    const uint32_t ONES2[2] = { 0x3C003C00u, 0x3C003C00u };

    for (int it = 0; it < NN / 64; it++) {
        if (it + 1 < NN / 64) { CPW(1); } else { CPW(0); }
        __syncthreads();
        const uint32_t skv = sb + F_KV + (it & 1) * FSTG;

        // ---- S = Qh*Kh ----
        float s[4][4];
#pragma unroll
        for (int j = 0; j < 4; j++)
#pragma unroll
            for (int c = 0; c < 4; c++) s[j][c] = 0.f;
#pragma unroll
        for (int ks = 0; ks < 4; ks++) {
            const int chk = ks * 2 + lc;
            uint32_t bhf[4][2];
#pragma unroll
            for (int jj = 0; jj < 2; jj++) {
                uint32_t q[4];
                ldsm4(skv + AOFF(wn * 32 + jj * 16 + lr, chk), q);
                bhf[jj * 2][0] = q[0]; bhf[jj * 2][1] = q[2];
                bhf[jj * 2 + 1][0] = q[1]; bhf[jj * 2 + 1][1] = q[3];
            }
#pragma unroll
            for (int j = 0; j < 4; j++)
                mma_hf(s[j], qh[ks], bhf[j]);
        }

        // ---- bias + WARP-LOCAL row max ----
        float mx0 = -1e30f, mx1 = -1e30f;
#pragma unroll
        for (int j = 0; j < 4; j++) {
            float2 mm = *(float2*)(m2s + it * 64 + wn * 32 + j * 8 + t * 2);
            s[j][0] = s[j][0] + m1r0 - mm.x;
            s[j][1] = s[j][1] + m1r0 - mm.y;
            s[j][2] = s[j][2] + m1r1 - mm.x;
            s[j][3] = s[j][3] + m1r1 - mm.y;
            mx0 = fmaxf(mx0, fmaxf(s[j][0], s[j][1]));
            mx1 = fmaxf(mx1, fmaxf(s[j][2], s[j][3]));
        }
        mx0 = fmaxf(mx0, __shfl_xor_sync(0xffffffffu, mx0, 1));
        mx0 = fmaxf(mx0, __shfl_xor_sync(0xffffffffu, mx0, 2));
        mx1 = fmaxf(mx1, __shfl_xor_sync(0xffffffffu, mx1, 1));
        mx1 = fmaxf(mx1, __shfl_xor_sync(0xffffffffu, mx1, 2));

        float mn0 = fmaxf(mst0, mx0), mn1 = fmaxf(mst1, mx1);
        float c0 = __expf(mst0 - mn0), c1 = __expf(mst1 - mn1);
        mst0 = mn0; mst1 = mn1;

#pragma unroll
        for (int j = 0; j < 8; j++) {
            o[j][0] *= c0; o[j][1] *= c0;
            o[j][2] *= c1; o[j][3] *= c1;
        }

        // ---- P = ex2((s-m)*L2E) packed fp16; O += P*Vh; l via ones-MMA ----
        float cl[4] = { 0.f, 0.f, 0.f, 0.f };
#pragma unroll
        for (int kks = 0; kks < 2; kks++) {
            const int j0 = 2 * kks, j1 = j0 + 1;
            uint32_t pah[4];
            pah[0] = ex2h2(pkh((s[j0][0] - mn0) * L2E, (s[j0][1] - mn0) * L2E));
            pah[1] = ex2h2(pkh((s[j0][2] - mn1) * L2E, (s[j0][3] - mn1) * L2E));
            pah[2] = ex2h2(pkh((s[j1][0] - mn0) * L2E, (s[j1][1] - mn0) * L2E));
            pah[3] = ex2h2(pkh((s[j1][2] - mn1) * L2E, (s[j1][3] - mn1) * L2E));

            mma_hf(cl, pah, ONES2);

            uint32_t vhf[8][2];
#pragma unroll
            for (int jj = 0; jj < 4; jj++) {
                uint32_t q[4];
                ldsm4t(skv + 8192 + AOFF(wn * 32 + kks * 16 + lr, jj * 2 + lc), q);
                vhf[jj * 2][0] = q[0]; vhf[jj * 2][1] = q[1];
                vhf[jj * 2 + 1][0] = q[2]; vhf[jj * 2 + 1][1] = q[3];
            }
#pragma unroll
            for (int j = 0; j < 8; j++)
                mma_hf(o[j], pah, vhf[j]);
        }
        l0 = l0 * c0 + cl[0];
        l1 = l1 * c1 + cl[2];

        __syncthreads();
        if (it + 2 < NN / 64) {
            kv_issue(sb, it & 1, it + 2, khp, vhp, tid); CPC();
        }
    }

    // ---- epilogue: merge halves, store ----
    __syncthreads();
    float* ob = (float*)(sm + F_OB);
    if (wn == 1) {
#pragma unroll
        for (int j = 0; j < 8; j++) {
            *(float2*)(ob + r0 * 68 + j * 8 + t * 2) = make_float2(o[j][0], o[j][1]);
            *(float2*)(ob + (r0 + 8) * 68 + j * 8 + t * 2) = make_float2(o[j][2], o[j][3]);
        }
        if (t == 0) {
            red[r0]      = l0;   red[r0 + 8]      = l1;
            red[64 + r0] = mst0; red[64 + r0 + 8] = mst1;
        }
    }
    __syncthreads();
    if (wn == 0) {
        float mB0 = red[64 + r0], mB1 = red[64 + r0 + 8];
        float lB0 = red[r0],      lB1 = red[r0 + 8];
        float m0f = fmaxf(mst0, mB0), m1f = fmaxf(mst1, mB1);
        float cA0 = __expf(mst0 - m0f), cB0 = __expf(mB0 - m0f);
        float cA1 = __expf(mst1 - m1f), cB1 = __expf(mB1 - m1f);
        float inv0 = 1.0f / (l0 * cA0 + lB0 * cB0);
        float inv1 = 1.0f / (l1 * cA1 + lB1 * cB1);
#pragma unroll
        for (int j = 0; j < 8; j++) {
            float2 u0 = *(float2*)(ob + r0 * 68 + j * 8 + t * 2);
            float2 u1 = *(float2*)(ob + (r0 + 8) * 68 + j * 8 + t * 2);
            float2 w0 = make_float2((o[j][0] * cA0 + u0.x * cB0) * inv0,
                                    (o[j][1] * cA0 + u0.y * cB0) * inv0);
            float2 w1 = make_float2((o[j][2] * cA1 + u1.x * cB1) * inv1,
                                    (o[j][3] * cA1 + u1.y * cB1) * inv1);
            size_t i0 = (size_t)(b * NN + mt * 64 + r0) * 384 + h * 32 + j * 4 + t;
            size_t i1 = (size_t)(b * NN + mt * 64 + r0 + 8) * 384 + h * 32 + j * 4 + t;
            g_aoh[i0] = pkh(w0.x, w0.y);
            g_aoh[i1] = pkh(w1.x, w1.y);
        }
    }
}

// ---------------------------------------------------------------------------
// LayerNorm(0.5*x1 + g_t)
// ---------------------------------------------------------------------------
__global__ __launch_bounds__(256) void ln_kernel(
    const float* __restrict__ x1, const float* __restrict__ gamma,
    const float* __restrict__ beta, float* __restrict__ out)
{
    const int row = blockIdx.x;
    const int tid = threadIdx.x;
    const float* tr = g_t + (size_t)row * NC;
    const float* xr = x1 + (size_t)row * NC;

    float z[3];
    float s = 0.f;
#pragma unroll
    for (int u = 0; u < 3; u++) {
        int idx = tid + u * 256;
        z[u] = 0.5f * xr[idx] + tr[idx];
        s += z[u];
    }

    __shared__ float red[8];
#pragma unroll
    for (int off = 16; off >= 1; off >>= 1) s += __shfl_xor_sync(0xffffffffu, s, off);
    if ((tid & 31) == 0) red[tid >> 5] = s;
    __syncthreads();
    float tot = 0.f;
#pragma unroll
    for (int w = 0; w < 8; w++) tot += red[w];
    const float mu = tot * (1.0f / NC);

    float s2 = 0.f;
#pragma unroll
    for (int u = 0; u < 3; u++) {
        float d = z[u] - mu;
        s2 += d * d;
    }
    __syncthreads();
#pragma unroll
    for (int off = 16; off >= 1; off >>= 1) s2 += __shfl_xor_sync(0xffffffffu, s2, off);
    if ((tid & 31) == 0) red[tid >> 5] = s2;
    __syncthreads();
    float tot2 = 0.f;
#pragma unroll
    for (int w = 0; w < 8; w++) tot2 += red[w];
    const float rstd = rsqrtf(tot2 * (1.0f / NC) + 1e-5f);

    float* orow = out + (size_t)row * NC;
#pragma unroll
    for (int u = 0; u < 3; u++) {
        int idx = tid + u * 256;
        orow[idx] = (z[u] - mu) * rstd * gamma[idx] + beta[idx];
    }
}

// ---------------------------------------------------------------------------
extern "C" void kernel_launch(void* const* d_in, const int* in_sizes, int n_in,
                              void* d_out, int out_size)
{
    (void)in_sizes; (void)n_in; (void)out_size;
    const float* x1    = (const float*)d_in[0];
    const float* x2    = (const float*)d_in[1];
    const float* mask1 = (const float*)d_in[2];
    const float* mask2 = (const float*)d_in[3];
    const float* Wq    = (const float*)d_in[4];
    const float* bq    = (const float*)d_in[5];
    const float* Wk    = (const float*)d_in[6];
    const float* bk    = (const float*)d_in[7];
    const float* Wv    = (const float*)d_in[8];
    const float* bv    = (const float*)d_in[9];
    const float* Wo    = (const float*)d_in[10];
    const float* bo    = (const float*)d_in[11];
    const float* temp  = (const float*)d_in[12];
    const float* gamma = (const float*)d_in[13];
    const float* beta  = (const float*)d_in[14];
    float* out = (float*)d_out;

    cudaFuncSetAttribute(mma_flash2,
                         cudaFuncAttributeMaxDynamicSharedMemorySize, ATT_SMEM);
    cudaFuncSetAttribute(mma_gemm2,
                         cudaFuncAttributeMaxDynamicSharedMemorySize, GEMM_SMEM);

    // prep: fused fp32 -> fp16 convert (single launch)
    split_all<<<(TOT4 + 255) / 256, 256>>>(x1, x2, Wq, Wk, Wv, Wo);

    // QKV projections (pure fp16, BK=64)
    mma_gemm2<<<dim3(NC / 128, (NB * NN) / 128, 3), 256, GEMM_SMEM>>>(bq, bk, bv, bo, 0);
    // attention (pure fp16, ex2.f16x2 softmax, ones-MMA row sums)
    mma_flash2<<<dim3(NN / 64, NB * NH), 256, ATT_SMEM>>>(mask1, mask2, temp);
    // output projection (pure fp16, BK=64)
    mma_gemm2<<<dim3(NC / 128, (NB * NN) / 128, 1), 256, GEMM_SMEM>>>(bq, bk, bv, bo, 1);
    ln_kernel<<<NB * NN, 256>>>(x1, gamma, beta, out);
}

// round 16
// speedup vs baseline: 2.4301x; 1.0867x over previous
#include <cuda_runtime.h>
#include <cstdint>

#define NB 4
#define NN 2048
#define NC 768
#define NH 12
#define ND 64
#define WPAIR (NC * NC / 2)        // 294912 uint32 pairs per weight matrix
#define XPAIR (NB * NN * NC / 2)   // 3145728
#define QPAIR (NB * NH * NN * ND / 2)

// ---------------- scratch (device globals; no allocation allowed) ----------
__device__ uint32_t g_wh[4 * WPAIR];                     // weights: fp16 (B side)
__device__ uint32_t g_x1h[XPAIR];                        // activations: fp16 (A side)
__device__ uint32_t g_x2h[XPAIR];
__device__ uint32_t g_qh[QPAIR];                         // Q: fp16 (x0.125)
__device__ uint32_t g_kh[QPAIR];                         // K: fp16
__device__ uint32_t g_vh[QPAIR];                         // V: fp16
__device__ uint32_t g_aoh[XPAIR];                        // attention out: fp16
__device__ float    g_t[NB * NN * NC];                   // oproj out (fp32 for LN)

// ======================= helpers (sm_80-level PTX only) =====================
static __device__ __forceinline__ uint32_t smem_u32(const void* p) {
    uint32_t a;
    asm("{ .reg .u64 t; cvta.to.shared.u64 t, %1; cvt.u32.u64 %0, t; }"
        : "=r"(a) : "l"(p));
    return a;
}
static __device__ __forceinline__ uint32_t pkh(float lo, float hi) {
    uint32_t r;
    asm("cvt.rn.f16x2.f32 %0, %1, %2;" : "=r"(r) : "f"(hi), "f"(lo));
    return r;
}
static __device__ __forceinline__ uint32_t ex2h2(uint32_t x) {
    uint32_t r;
    asm("ex2.approx.f16x2 %0, %1;" : "=r"(r) : "r"(x));
    return r;
}
static __device__ __forceinline__ void ldsm4(uint32_t a, uint32_t* r) {
    asm volatile("ldmatrix.sync.aligned.m8n8.x4.shared.b16 {%0,%1,%2,%3}, [%4];"
                 : "=r"(r[0]), "=r"(r[1]), "=r"(r[2]), "=r"(r[3]) : "r"(a));
}
static __device__ __forceinline__ void ldsm4t(uint32_t a, uint32_t* r) {
    asm volatile("ldmatrix.sync.aligned.m8n8.x4.trans.shared.b16 {%0,%1,%2,%3}, [%4];"
                 : "=r"(r[0]), "=r"(r[1]), "=r"(r[2]), "=r"(r[3]) : "r"(a));
}
static __device__ __forceinline__ void mma_hf(float* c, const uint32_t* a, const uint32_t* b) {
    asm volatile("mma.sync.aligned.m16n8k16.row.col.f32.f16.f16.f32 "
                 "{%0,%1,%2,%3},{%4,%5,%6,%7},{%8,%9},{%0,%1,%2,%3};"
                 : "+f"(c[0]), "+f"(c[1]), "+f"(c[2]), "+f"(c[3])
                 : "r"(a[0]), "r"(a[1]), "r"(a[2]), "r"(a[3]),
                   "r"(b[0]), "r"(b[1]));
}
#define CPA(dst, src) \
    asm volatile("cp.async.cg.shared.global [%0], [%1], 16;" :: "r"(dst), "l"(src))
#define CPC() asm volatile("cp.async.commit_group;" ::: "memory")
#define CPW(n) asm volatile("cp.async.wait_group %0;" :: "n"(n) : "memory")

// 128B-row swizzled smem byte offset (rows of 64 fp16)
#define AOFF(r, ch) (((r) * 128) + ((((ch) ^ ((r) & 7))) * 16))

// ======================= prep: fused fp32 -> fp16 convert ===================
#define XN4 (NB * NN * NC / 4)
#define WN4 (NC * NC / 4)
#define TOT4 (2 * XN4 + 4 * WN4)

__global__ __launch_bounds__(256) void split_all(
    const float* __restrict__ x1, const float* __restrict__ x2,
    const float* __restrict__ Wq, const float* __restrict__ Wk,
    const float* __restrict__ Wv, const float* __restrict__ Wo)
{
    int i = blockIdx.x * blockDim.x + threadIdx.x;
    if (i >= TOT4) return;
    const float* src; uint32_t* dh; int li;
    if (i < XN4)          { src = x1; dh = g_x1h; li = i; }
    else if (i < 2 * XN4) { src = x2; dh = g_x2h; li = i - XN4; }
    else {
        int j = i - 2 * XN4;
        int w = j / WN4;
        li = j - w * WN4;
        src = (w == 0) ? Wq : (w == 1) ? Wk : (w == 2) ? Wv : Wo;
        dh = g_wh + (size_t)w * WPAIR;
    }
    float4 f = ((const float4*)src)[li];
    ((uint2*)dh)[li] = make_uint2(pkh(f.x, f.y), pkh(f.z, f.w));
}

// ======================= pure-fp16 mma GEMM (BK=64, R14-proven) ==============
#define GSTG 32768
#define GEMM_SMEM (2 * GSTG)      // 65536

static __device__ __forceinline__ void gemm_issue(
    uint32_t sb, int buf, int c, const uint32_t* Ah,
    const uint32_t* Wh, int m0, int n0, int tid)
{
#pragma unroll
    for (int p = 0; p < 4; p++) {
        int cid = tid + p * 256;
        int r = cid >> 3, ch = cid & 7;
        size_t sa = (size_t)(m0 + r) * 384 + c * 32 + ch * 4;
        size_t sw = (size_t)(n0 + r) * 384 + c * 32 + ch * 4;
        uint32_t d = sb + buf * GSTG + AOFF(r, ch);
        CPA(d,         Ah + sa);
        CPA(d + 16384, Wh + sw);
    }
}

__global__ __launch_bounds__(256) void mma_gemm2(
    const float* __restrict__ bq, const float* __restrict__ bk,
    const float* __restrict__ bv, const float* __restrict__ bo, int phase)
{
    extern __shared__ __align__(128) char gsm[];
    const uint32_t sb = smem_u32(gsm);
    const int mode = phase ? 3 : (int)blockIdx.z;
    const uint32_t* Ah = (mode == 0) ? g_x1h : (mode == 3) ? g_aoh : g_x2h;
    const uint32_t* Wh = g_wh + (size_t)mode * WPAIR;
    const float* bias = (mode == 0) ? bq : (mode == 1) ? bk : (mode == 2) ? bv : bo;

    const int n0 = blockIdx.x * 128;
    const int m0 = blockIdx.y * 128;
    const int tid  = threadIdx.x;
    const int lane = tid & 31;
    const int wid  = tid >> 5;
    const int wm = wid & 3;
    const int wn = wid >> 2;
    const int g  = lane >> 2;
    const int t  = lane & 3;
    const int lr = lane & 15;
    const int lc = lane >> 4;

    float acc[2][8][4];
#pragma unroll
    for (int i = 0; i < 2; i++)
#pragma unroll
        for (int j = 0; j < 8; j++)
#pragma unroll
            for (int c = 0; c < 4; c++) acc[i][j][c] = 0.f;

    gemm_issue(sb, 0, 0, Ah, Wh, m0, n0, tid); CPC();
    gemm_issue(sb, 1, 1, Ah, Wh, m0, n0, tid); CPC();

    for (int c = 0; c < NC / 64; c++) {
        if (c + 1 < NC / 64) { CPW(1); } else { CPW(0); }
        __syncthreads();
        const uint32_t s2 = sb + (c & 1) * GSTG;

#pragma unroll
        for (int ks = 0; ks < 4; ks++) {
            const int chk = ks * 2 + lc;
            uint32_t ah[2][4], bh[8][2];
#pragma unroll
            for (int mf = 0; mf < 2; mf++)
                ldsm4(s2 + AOFF(wm * 32 + mf * 16 + lr, chk), ah[mf]);
#pragma unroll
            for (int jj = 0; jj < 4; jj++) {
                uint32_t q[4];
                ldsm4(s2 + 16384 + AOFF(wn * 64 + jj * 16 + lr, chk), q);
                bh[jj * 2][0] = q[0]; bh[jj * 2][1] = q[2];
                bh[jj * 2 + 1][0] = q[1]; bh[jj * 2 + 1][1] = q[3];
            }
#pragma unroll
            for (int mf = 0; mf < 2; mf++)
#pragma unroll
                for (int j = 0; j < 8; j++)
                    mma_hf(acc[mf][j], ah[mf], bh[j]);
        }
        __syncthreads();
        if (c + 2 < NC / 64) {
            gemm_issue(sb, c & 1, c + 2, Ah, Wh, m0, n0, tid); CPC();
        }
    }

#pragma unroll
    for (int mf = 0; mf < 2; mf++) {
        int r = m0 + wm * 32 + mf * 16 + g;
#pragma unroll
        for (int j = 0; j < 8; j++) {
            int cg = n0 + wn * 64 + j * 8 + t * 2;
            float bx = bias[cg], by = bias[cg + 1];
            float2 v0 = { acc[mf][j][0] + bx, acc[mf][j][1] + by };
            float2 v1 = { acc[mf][j][2] + bx, acc[mf][j][3] + by };
            if (mode == 3) {
                *(float2*)(g_t + (size_t)r * NC + cg) = v0;
                *(float2*)(g_t + (size_t)(r + 8) * NC + cg) = v1;
            } else {
                int b = r >> 11, h = cg >> 6, dp = (cg & 63) >> 1;
                size_t base = ((size_t)(b * NH + h)) * NN;
                size_t i0 = (base + (r & (NN - 1))) * 32 + dp;
                size_t i1 = (base + ((r + 8) & (NN - 1))) * 32 + dp;
                if (mode == 0) {
                    v0.x *= 0.125f; v0.y *= 0.125f;
                    v1.x *= 0.125f; v1.y *= 0.125f;
                    g_qh[i0] = pkh(v0.x, v0.y);
                    g_qh[i1] = pkh(v1.x, v1.y);
                } else {
                    uint32_t* dst = (mode == 1) ? g_kh : g_vh;
                    dst[i0] = pkh(v0.x, v0.y);
                    dst[i1] = pkh(v1.x, v1.y);
                }
            }
        }
    }
}

// ======================= pure-fp16 mma flash attention (KV tile 128) =========
// CTA 64 Q-rows; 8 warps 4(M)x2(N); each N-half owns 64 of the 128 KV cols per
// tile (disjoint col sets overall -> independent softmax halves, merged once).
// 16 iterations of 128 KV positions: per-iter overheads halved vs KV=64.
// smem: m2 8K | red 512 | Qhi 8K | KV stages 2x32K (Kh 16K | Vh 16K)
#define F_M2  0
#define F_RED 8192
#define F_QH  8704
#define F_KV  16896
#define F_OB  16896                       // aliases KV (used only after loop)
#define FSTG  32768
#define ATT_SMEM (F_KV + 2 * FSTG)        // 82432

static __device__ __forceinline__ void kv_issue(
    uint32_t sb, int buf, int it, const uint32_t* kh, const uint32_t* vh, int tid)
{
#pragma unroll
    for (int p = 0; p < 4; p++) {
        int cid = tid + p * 256;
        int r = cid >> 3, ch = cid & 7;       // 128 rows x 8 chunks
        size_t src = (size_t)(it * 128 + r) * 32 + ch * 4;
        uint32_t d = sb + F_KV + buf * FSTG + AOFF(r, ch);
        CPA(d,         kh + src);
        CPA(d + 16384, vh + src);
    }
}

__global__ __launch_bounds__(256, 2) void mma_flash2(
    const float* __restrict__ mask1, const float* __restrict__ mask2,
    const float* __restrict__ temp_p)
{
    extern __shared__ __align__(128) char sm[];
    const uint32_t sb = smem_u32(sm);
    const int mt = blockIdx.x;
    const int bh = blockIdx.y;
    const int b  = bh / NH;
    const int h  = bh % NH;
    const int tid  = threadIdx.x;
    const int lane = tid & 31;
    const int wid  = tid >> 5;
    const int wm = wid & 3;
    const int wn = wid >> 2;
    const int g  = lane >> 2;
    const int t  = lane & 3;
    const int lr = lane & 15;
    const int lc = lane >> 4;

    const float itemp = 1.0f / temp_p[0];
    const float L2E = 1.4426950408889634f;

    const uint32_t* qhp = g_qh + ((size_t)bh * NN + mt * 64) * 32;
    const uint32_t* khp = g_kh + (size_t)bh * NN * 32;
    const uint32_t* vhp = g_vh + (size_t)bh * NN * 32;

    // Q tile (group 0)
    {
        int cid = tid;
        int r = cid >> 2, ch = (cid & 3) << 1;
        size_t src = (size_t)r * 32 + ch * 4;
        CPA(sb + F_QH + AOFF(r, ch),     qhp + src);
        CPA(sb + F_QH + AOFF(r, ch + 1), qhp + src + 4);
    }
    CPC();
    kv_issue(sb, 0, 0, khp, vhp, tid); CPC();
    kv_issue(sb, 1, 1, khp, vhp, tid); CPC();

    // mask2 row -> smem (x itemp), once
    float* m2s = (float*)(sm + F_M2);
    for (int i = tid; i < NN / 4; i += 256) {
        float4 f = *(const float4*)(mask2 + b * NN + i * 4);
        float4 gg = { f.x * itemp, f.y * itemp, f.z * itemp, f.w * itemp };
        *(float4*)(m2s + i * 4) = gg;
    }

    CPW(2);            // Q arrived
    __syncthreads();

    uint32_t qh[4][4];
#pragma unroll
    for (int ks = 0; ks < 4; ks++)
        ldsm4(sb + F_QH + AOFF(wm * 16 + lr, ks * 2 + lc), qh[ks]);

    const float m1r0 = mask1[b * NN + mt * 64 + wm * 16 + g] * itemp;
    const float m1r1 = mask1[b * NN + mt * 64 + wm * 16 + 8 + g] * itemp;

    float o[8][4];
#pragma unroll
    for (int j = 0; j < 8; j++)
#pragma unroll
        for (int c = 0; c < 4; c++) o[j][c] = 0.f;
    float mst0 = -1e30f, mst1 = -1e30f, l0 = 0.f, l1 = 0.f;

    float* red = (float*)(sm + F_RED);
    const int r0 = wm * 16 + g;
    const uint32_t ONES2[2] = { 0x3C003C00u, 0x3C003C00u };

    for (int it = 0; it < NN / 128; it++) {
        if (it + 1 < NN / 128) { CPW(1); } else { CPW(0); }
        __syncthreads();
        const uint32_t skv = sb + F_KV + (it & 1) * FSTG;

        // ---- S = Qh*Kh over this half's 64 cols (8 n-frags) ----
        float s[8][4];
#pragma unroll
        for (int j = 0; j < 8; j++)
#pragma unroll
            for (int c = 0; c < 4; c++) s[j][c] = 0.f;
#pragma unroll
        for (int ks = 0; ks < 4; ks++) {
            const int chk = ks * 2 + lc;
            uint32_t bhf[8][2];
#pragma unroll
            for (int jj = 0; jj < 4; jj++) {
                uint32_t q[4];
                ldsm4(skv + AOFF(wn * 64 + jj * 16 + lr, chk), q);
                bhf[jj * 2][0] = q[0]; bhf[jj * 2][1] = q[2];
                bhf[jj * 2 + 1][0] = q[1]; bhf[jj * 2 + 1][1] = q[3];
            }
#pragma unroll
            for (int j = 0; j < 8; j++)
                mma_hf(s[j], qh[ks], bhf[j]);
        }

        // ---- bias + WARP-LOCAL row max over 64 cols ----
        float mx0 = -1e30f, mx1 = -1e30f;
#pragma unroll
        for (int j = 0; j < 8; j++) {
            float2 mm = *(float2*)(m2s + it * 128 + wn * 64 + j * 8 + t * 2);
            s[j][0] = s[j][0] + m1r0 - mm.x;
            s[j][1] = s[j][1] + m1r0 - mm.y;
            s[j][2] = s[j][2] + m1r1 - mm.x;
            s[j][3] = s[j][3] + m1r1 - mm.y;
            mx0 = fmaxf(mx0, fmaxf(s[j][0], s[j][1]));
            mx1 = fmaxf(mx1, fmaxf(s[j][2], s[j][3]));
        }
        mx0 = fmaxf(mx0, __shfl_xor_sync(0xffffffffu, mx0, 1));
        mx0 = fmaxf(mx0, __shfl_xor_sync(0xffffffffu, mx0, 2));
        mx1 = fmaxf(mx1, __shfl_xor_sync(0xffffffffu, mx1, 1));
        mx1 = fmaxf(mx1, __shfl_xor_sync(0xffffffffu, mx1, 2));

        float mn0 = fmaxf(mst0, mx0), mn1 = fmaxf(mst1, mx1);
        float c0 = __expf(mst0 - mn0), c1 = __expf(mst1 - mn1);
        mst0 = mn0; mst1 = mn1;

#pragma unroll
        for (int j = 0; j < 8; j++) {
            o[j][0] *= c0; o[j][1] *= c0;
            o[j][2] *= c1; o[j][3] *= c1;
        }

        // ---- P = ex2((s-m)*L2E); O += P*Vh; l via ones-MMA ----
        float cl[4] = { 0.f, 0.f, 0.f, 0.f };
#pragma unroll
        for (int kks = 0; kks < 4; kks++) {
            const int j0 = 2 * kks, j1 = j0 + 1;
            uint32_t pah[4];
            pah[0] = ex2h2(pkh((s[j0][0] - mn0) * L2E, (s[j0][1] - mn0) * L2E));
            pah[1] = ex2h2(pkh((s[j0][2] - mn1) * L2E, (s[j0][3] - mn1) * L2E));
            pah[2] = ex2h2(pkh((s[j1][0] - mn0) * L2E, (s[j1][1] - mn0) * L2E));
            pah[3] = ex2h2(pkh((s[j1][2] - mn1) * L2E, (s[j1][3] - mn1) * L2E));

            mma_hf(cl, pah, ONES2);

            uint32_t vhf[8][2];
#pragma unroll
            for (int jj = 0; jj < 4; jj++) {
                uint32_t q[4];
                ldsm4t(skv + 16384 + AOFF(wn * 64 + kks * 16 + lr, jj * 2 + lc), q);
                vhf[jj * 2][0] = q[0]; vhf[jj * 2][1] = q[1];
                vhf[jj * 2 + 1][0] = q[2]; vhf[jj * 2 + 1][1] = q[3];
            }
#pragma unroll
            for (int j = 0; j < 8; j++)
                mma_hf(o[j], pah, vhf[j]);
        }
        l0 = l0 * c0 + cl[0];
        l1 = l1 * c1 + cl[2];

        __syncthreads();
        if (it + 2 < NN / 128) {
            kv_issue(sb, it & 1, it + 2, khp, vhp, tid); CPC();
        }
    }

    // ---- epilogue: merge halves, store ----
    __syncthreads();
    float* ob = (float*)(sm + F_OB);
    if (wn == 1) {
#pragma unroll
        for (int j = 0; j < 8; j++) {
            *(float2*)(ob + r0 * 68 + j * 8 + t * 2) = make_float2(o[j][0], o[j][1]);
            *(float2*)(ob + (r0 + 8) * 68 + j * 8 + t * 2) = make_float2(o[j][2], o[j][3]);
        }
        if (t == 0) {
            red[r0]      = l0;   red[r0 + 8]      = l1;
            red[64 + r0] = mst0; red[64 + r0 + 8] = mst1;
        }
    }
    __syncthreads();
    if (wn == 0) {
        float mB0 = red[64 + r0], mB1 = red[64 + r0 + 8];
        float lB0 = red[r0],      lB1 = red[r0 + 8];
        float m0f = fmaxf(mst0, mB0), m1f = fmaxf(mst1, mB1);
        float cA0 = __expf(mst0 - m0f), cB0 = __expf(mB0 - m0f);
        float cA1 = __expf(mst1 - m1f), cB1 = __expf(mB1 - m1f);
        float inv0 = 1.0f / (l0 * cA0 + lB0 * cB0);
        float inv1 = 1.0f / (l1 * cA1 + lB1 * cB1);
#pragma unroll
        for (int j = 0; j < 8; j++) {
            float2 u0 = *(float2*)(ob + r0 * 68 + j * 8 + t * 2);
            float2 u1 = *(float2*)(ob + (r0 + 8) * 68 + j * 8 + t * 2);
            float2 w0 = make_float2((o[j][0] * cA0 + u0.x * cB0) * inv0,
                                    (o[j][1] * cA0 + u0.y * cB0) * inv0);
            float2 w1 = make_float2((o[j][2] * cA1 + u1.x * cB1) * inv1,
                                    (o[j][3] * cA1 + u1.y * cB1) * inv1);
            size_t i0 = (size_t)(b * NN + mt * 64 + r0) * 384 + h * 32 + j * 4 + t;
            size_t i1 = (size_t)(b * NN + mt * 64 + r0 + 8) * 384 + h * 32 + j * 4 + t;
            g_aoh[i0] = pkh(w0.x, w0.y);
            g_aoh[i1] = pkh(w1.x, w1.y);
        }
    }
}

// ---------------------------------------------------------------------------
// LayerNorm(0.5*x1 + g_t)
// ---------------------------------------------------------------------------
__global__ __launch_bounds__(256) void ln_kernel(
    const float* __restrict__ x1, const float* __restrict__ gamma,
    const float* __restrict__ beta, float* __restrict__ out)
{
    const int row = blockIdx.x;
    const int tid = threadIdx.x;
    const float* tr = g_t + (size_t)row * NC;
    const float* xr = x1 + (size_t)row * NC;

    float z[3];
    float s = 0.f;
#pragma unroll
    for (int u = 0; u < 3; u++) {
        int idx = tid + u * 256;
        z[u] = 0.5f * xr[idx] + tr[idx];
        s += z[u];
    }

    __shared__ float red[8];
#pragma unroll
    for (int off = 16; off >= 1; off >>= 1) s += __shfl_xor_sync(0xffffffffu, s, off);
    if ((tid & 31) == 0) red[tid >> 5] = s;
    __syncthreads();
    float tot = 0.f;
#pragma unroll
    for (int w = 0; w < 8; w++) tot += red[w];
    const float mu = tot * (1.0f / NC);

    float s2 = 0.f;
#pragma unroll
    for (int u = 0; u < 3; u++) {
        float d = z[u] - mu;
        s2 += d * d;
    }
    __syncthreads();
#pragma unroll
    for (int off = 16; off >= 1; off >>= 1) s2 += __shfl_xor_sync(0xffffffffu, s2, off);
    if ((tid & 31) == 0) red[tid >> 5] = s2;
    __syncthreads();
    float tot2 = 0.f;
#pragma unroll
    for (int w = 0; w < 8; w++) tot2 += red[w];
    const float rstd = rsqrtf(tot2 * (1.0f / NC) + 1e-5f);

    float* orow = out + (size_t)row * NC;
#pragma unroll
    for (int u = 0; u < 3; u++) {
        int idx = tid + u * 256;
        orow[idx] = (z[u] - mu) * rstd * gamma[idx] + beta[idx];
    }
}

// ---------------------------------------------------------------------------
extern "C" void kernel_launch(void* const* d_in, const int* in_sizes, int n_in,
                              void* d_out, int out_size)
{
    (void)in_sizes; (void)n_in; (void)out_size;
    const float* x1    = (const float*)d_in[0];
    const float* x2    = (const float*)d_in[1];
    const float* mask1 = (const float*)d_in[2];
    const float* mask2 = (const float*)d_in[3];
    const float* Wq    = (const float*)d_in[4];
    const float* bq    = (const float*)d_in[5];
    const float* Wk    = (const float*)d_in[6];
    const float* bk    = (const float*)d_in[7];
    const float* Wv    = (const float*)d_in[8];
    const float* bv    = (const float*)d_in[9];
    const float* Wo    = (const float*)d_in[10];
    const float* bo    = (const float*)d_in[11];
    const float* temp  = (const float*)d_in[12];
    const float* gamma = (const float*)d_in[13];
    const float* beta  = (const float*)d_in[14];
    float* out = (float*)d_out;

    cudaFuncSetAttribute(mma_flash2,
                         cudaFuncAttributeMaxDynamicSharedMemorySize, ATT_SMEM);
    cudaFuncSetAttribute(mma_gemm2,
                         cudaFuncAttributeMaxDynamicSharedMemorySize, GEMM_SMEM);

    // prep: fused fp32 -> fp16 convert (single launch)
    split_all<<<(TOT4 + 255) / 256, 256>>>(x1, x2, Wq, Wk, Wv, Wo);

    // QKV projections (pure fp16, BK=64)
    mma_gemm2<<<dim3(NC / 128, (NB * NN) / 128, 3), 256, GEMM_SMEM>>>(bq, bk, bv, bo, 0);
    // attention (pure fp16, KV tile 128, ex2.f16x2 softmax, ones-MMA row sums)
    mma_flash2<<<dim3(NN / 64, NB * NH), 256, ATT_SMEM>>>(mask1, mask2, temp);
    // output projection (pure fp16, BK=64)
    mma_gemm2<<<dim3(NC / 128, (NB * NN) / 128, 1), 256, GEMM_SMEM>>>(bq, bk, bv, bo, 1);
    ln_kernel<<<NB * NN, 256>>>(x1, gamma, beta, out);
}